// round 1
// baseline (speedup 1.0000x reference)
#include <cuda_runtime.h>
#include <cuda_bf16.h>

#define NN 100000
#define NE 1600000
#define NTOT (NE + NN)

// ---------------- scratch (device globals: allocation-free) ----------------
__device__ float g_bufA[NN * 160];
__device__ float g_bufB[NN * 160];
__device__ int   g_cnt[NN];
__device__ float g_dis[NN];
__device__ int   g_rowptr[NN + 1];
__device__ int   g_fill[NN];
__device__ int2  g_entries[NTOT];   // {src_node, float_bits(norm)} sorted by dst
__device__ int   g_bsums[128];

static inline int cdiv(int a, int b) { return (a + b - 1) / b; }

// ---------------- CSR build ----------------
__global__ void k_init_cnt() {
    int i = blockIdx.x * blockDim.x + threadIdx.x;
    if (i < NN) g_cnt[i] = 1;   // self-loop
}
__global__ void k_count(const int* __restrict__ dst) {
    int e = blockIdx.x * blockDim.x + threadIdx.x;
    if (e < NE) atomicAdd(&g_cnt[dst[e]], 1);
}
__global__ void k_dis() {
    int i = blockIdx.x * blockDim.x + threadIdx.x;
    if (i < NN) g_dis[i] = rsqrtf((float)g_cnt[i]);
}
// inclusive scan within 1024-elem blocks
__global__ void k_scan1() {
    __shared__ int s[1024];
    int i = blockIdx.x * 1024 + threadIdx.x;
    int v = (i < NN) ? g_cnt[i] : 0;
    s[threadIdx.x] = v;
    __syncthreads();
    for (int d = 1; d < 1024; d <<= 1) {
        int t = (threadIdx.x >= d) ? s[threadIdx.x - d] : 0;
        __syncthreads();
        s[threadIdx.x] += t;
        __syncthreads();
    }
    if (i < NN) g_rowptr[i + 1] = s[threadIdx.x];
    if (threadIdx.x == 1023) g_bsums[blockIdx.x] = s[1023];
}
__global__ void k_scan2(int nb) {   // exclusive scan of block sums (nb <= 128)
    __shared__ int s[128];
    int v = (threadIdx.x < nb) ? g_bsums[threadIdx.x] : 0;
    s[threadIdx.x] = v;
    __syncthreads();
    for (int d = 1; d < 128; d <<= 1) {
        int t = (threadIdx.x >= d) ? s[threadIdx.x - d] : 0;
        __syncthreads();
        s[threadIdx.x] += t;
        __syncthreads();
    }
    if (threadIdx.x < nb) g_bsums[threadIdx.x] = s[threadIdx.x] - v;
}
__global__ void k_scan3() {
    int i = blockIdx.x * 1024 + threadIdx.x;
    if (i < NN) g_rowptr[i + 1] += g_bsums[blockIdx.x];
    if (i == 0) g_rowptr[0] = 0;
}
__global__ void k_fill_init() {
    int i = blockIdx.x * blockDim.x + threadIdx.x;
    if (i < NN) g_fill[i] = g_rowptr[i];
}
__global__ void k_self() {
    int i = blockIdx.x * blockDim.x + threadIdx.x;
    if (i < NN) {
        int p = atomicAdd(&g_fill[i], 1);
        float d = g_dis[i];
        g_entries[p] = make_int2(i, __float_as_int(d * d));
    }
}
__global__ void k_edges(const int* __restrict__ src, const int* __restrict__ dst) {
    int e = blockIdx.x * blockDim.x + threadIdx.x;
    if (e < NE) {
        int s = src[e], d = dst[e];
        int p = atomicAdd(&g_fill[d], 1);
        g_entries[p] = make_int2(s, __float_as_int(g_dis[s] * g_dis[d]));
    }
}

// ---------------- aggregation: out[n][c] = sum_row norm * in[src][c] ----------------
// SUB lanes per node; ACT: 0 none, 1 relu, 2 tanh
template <int C, int SUB, int ACT, bool BIAS>
__global__ void k_agg(const float* __restrict__ in, const float* __restrict__ bias,
                      float* __restrict__ out) {
    const int nodesPerWarp = 32 / SUB;
    int gwarp = (blockIdx.x * blockDim.x + threadIdx.x) >> 5;
    int lane = threadIdx.x & 31;
    int node = gwarp * nodesPerWarp + lane / SUB;
    int cl = lane % SUB;
    if (node >= NN) return;
    int p0 = g_rowptr[node], p1 = g_rowptr[node + 1];
    constexpr int NACC = (C + SUB - 1) / SUB;
    float acc[NACC];
#pragma unroll
    for (int j = 0; j < NACC; j++) acc[j] = 0.f;
    for (int p = p0; p < p1; p++) {
        int2 e = __ldg(&g_entries[p]);
        float w = __int_as_float(e.y);
        const float* fp = in + (long)e.x * C;
#pragma unroll
        for (int j = 0; j < NACC; j++) {
            int c = cl + j * SUB;
            if (c < C) acc[j] = fmaf(w, __ldg(fp + c), acc[j]);
        }
    }
#pragma unroll
    for (int j = 0; j < NACC; j++) {
        int c = cl + j * SUB;
        if (c < C) {
            float v = acc[j];
            if (BIAS) v += bias[c];
            if (ACT == 1) v = fmaxf(v, 0.f);
            if (ACT == 2) v = tanhf(v);
            out[(long)node * C + c] = v;
        }
    }
}

// ---------------- GEMM: out = act(A[M,K] @ W[K,Nc] + b) ----------------
#define BM 64
#define BN 64
#define BK 16
#define TM 4
#define TN 4
__global__ void __launch_bounds__(256)
k_gemm(const float* __restrict__ A, const float* __restrict__ W,
       const float* __restrict__ bias, float* __restrict__ out,
       int M, int K, int Nc, int act, int useBias) {
    __shared__ float sA[BK][BM + 1];
    __shared__ float sW[BK][BN];
    int tx = threadIdx.x % 16, ty = threadIdx.x / 16;
    int row0 = blockIdx.y * BM, col0 = blockIdx.x * BN;
    float acc[TM][TN] = {};
    for (int k0 = 0; k0 < K; k0 += BK) {
        for (int i = threadIdx.x; i < BM * BK; i += 256) {
            int kk = i % BK, m = i / BK;
            int gm = row0 + m, gk = k0 + kk;
            sA[kk][m] = (gm < M && gk < K) ? A[(long)gm * K + gk] : 0.f;
        }
        for (int i = threadIdx.x; i < BK * BN; i += 256) {
            int n = i % BN, kk = i / BN;
            int gk = k0 + kk, gn = col0 + n;
            sW[kk][n] = (gk < K && gn < Nc) ? W[gk * Nc + gn] : 0.f;
        }
        __syncthreads();
#pragma unroll
        for (int kk = 0; kk < BK; kk++) {
            float a[TM];
#pragma unroll
            for (int i = 0; i < TM; i++) a[i] = sA[kk][ty * TM + i];
            float4 w4 = *(const float4*)&sW[kk][tx * TN];
            float w[TN] = {w4.x, w4.y, w4.z, w4.w};
#pragma unroll
            for (int i = 0; i < TM; i++)
#pragma unroll
                for (int j = 0; j < TN; j++) acc[i][j] = fmaf(a[i], w[j], acc[i][j]);
        }
        __syncthreads();
    }
#pragma unroll
    for (int i = 0; i < TM; i++) {
        int gm = row0 + ty * TM + i;
        if (gm >= M) continue;
#pragma unroll
        for (int j = 0; j < TN; j++) {
            int gn = col0 + tx * TN + j;
            if (gn >= Nc) continue;
            float v = acc[i][j];
            if (useBias) v += bias[gn];
            if (act == 1) v = fmaxf(v, 0.f);
            else if (act == 2) v = tanhf(v);
            out[(long)gm * Nc + gn] = v;
        }
    }
}

// ---------------- driver ----------------
static void gemm(const float* A, const float* W, const float* b, float* o,
                 int K, int Nc, int act, int useBias) {
    dim3 g(cdiv(Nc, BN), cdiv(NN, BM));
    k_gemm<<<g, 256>>>(A, W, b, o, NN, K, Nc, act, useBias);
}

extern "C" void kernel_launch(void* const* d_in, const int* in_sizes, int n_in,
                              void* d_out, int out_size) {
    const float* x = (const float*)d_in[0];
    const int* ei = (const int*)d_in[1];
    const int* src = ei;
    const int* dst = ei + NE;
    const float* W[12];
    const float* B[12];
    for (int i = 0; i < 12; i++) {
        W[i] = (const float*)d_in[2 + 2 * i];
        B[i] = (const float*)d_in[3 + 2 * i];
    }
    float* bufA; cudaGetSymbolAddress((void**)&bufA, g_bufA);
    float* bufB; cudaGetSymbolAddress((void**)&bufB, g_bufB);
    float* outp = (float*)d_out;

    const int NB = cdiv(NN, 1024);
    // CSR build
    k_init_cnt<<<cdiv(NN, 256), 256>>>();
    k_count<<<cdiv(NE, 256), 256>>>(dst);
    k_dis<<<cdiv(NN, 256), 256>>>();
    k_scan1<<<NB, 1024>>>();
    k_scan2<<<1, 128>>>(NB);
    k_scan3<<<NB, 1024>>>();
    k_fill_init<<<cdiv(NN, 256), 256>>>();
    k_self<<<cdiv(NN, 256), 256>>>();
    k_edges<<<cdiv(NE, 256), 256>>>(src, dst);

    const int TPB = 256;
    int warps32 = NN;                       // 1 node per warp
    int blocks32 = cdiv(warps32 * 32, TPB);
    int warps4 = cdiv(NN, 8);               // 8 nodes per warp (SUB=4)
    int blocks4 = cdiv(warps4 * 32, TPB);

    // encoder GCN
    k_agg<3, 4, 0, false><<<blocks4, TPB>>>(x, nullptr, bufA);        // agg(x), C=3
    gemm(bufA, W[0], B[0], bufB, 3, 160, 1, 1);                       // eg1: relu(a@W+b)
    gemm(bufB, W[1], nullptr, bufA, 160, 80, 0, 0);                   // eg2 matmul
    k_agg<80, 32, 1, true><<<blocks32, TPB>>>(bufA, B[1], bufB);      // eg2 agg+b+relu
    gemm(bufB, W[2], nullptr, bufA, 80, 40, 0, 0);                    // eg3
    k_agg<40, 32, 1, true><<<blocks32, TPB>>>(bufA, B[2], bufB);
    gemm(bufB, W[3], nullptr, bufA, 40, 20, 0, 0);                    // eg4
    k_agg<20, 32, 1, true><<<blocks32, TPB>>>(bufA, B[3], bufB);
    // dense latent
    gemm(bufB, W[4], B[4], bufA, 20, 10, 1, 1);                       // el1
    gemm(bufA, W[5], B[5], bufB, 10, 3, 0, 1);                        // el2
    gemm(bufB, W[6], B[6], bufA, 3, 10, 1, 1);                        // dl1
    gemm(bufA, W[7], B[7], bufB, 10, 20, 1, 1);                       // dl2
    // decoder GCN
    k_agg<20, 32, 0, false><<<blocks32, TPB>>>(bufB, nullptr, bufA);  // dg1 agg first
    gemm(bufA, W[8], B[8], bufB, 20, 40, 1, 1);
    k_agg<40, 32, 0, false><<<blocks32, TPB>>>(bufB, nullptr, bufA);  // dg2
    gemm(bufA, W[9], B[9], bufB, 40, 80, 1, 1);
    k_agg<80, 32, 0, false><<<blocks32, TPB>>>(bufB, nullptr, bufA);  // dg3
    gemm(bufA, W[10], B[10], bufB, 80, 160, 1, 1);
    gemm(bufB, W[11], nullptr, bufA, 160, 3, 0, 0);                   // dg4 matmul
    k_agg<3, 4, 2, true><<<blocks4, TPB>>>(bufA, B[11], outp);        // dg4 agg+b+tanh
}

// round 2
// speedup vs baseline: 1.2104x; 1.2104x over previous
#include <cuda_runtime.h>
#include <cuda_bf16.h>
#include <cstdint>

#define NN 100000
#define NE 1600000
#define NTOT (NE + NN)

// ---------------- scratch (device globals: allocation-free) ----------------
__device__ float g_bufA[NN * 160];
__device__ float g_bufB[NN * 160];
__device__ int   g_cnt[NN];
__device__ float g_dis[NN];
__device__ int   g_rowptr[NN + 1];
__device__ int   g_fill[NN];
__device__ int2  g_entries[NTOT];   // {src_node, float_bits(norm)} sorted by dst
__device__ int   g_bsums[128];

static inline int cdiv(int a, int b) { return (a + b - 1) / b; }

// ---------------- CSR build ----------------
__global__ void k_init_cnt() {
    int i = blockIdx.x * blockDim.x + threadIdx.x;
    if (i < NN) g_cnt[i] = 1;   // self-loop
}
__global__ void k_count(const int* __restrict__ dst) {
    int e = blockIdx.x * blockDim.x + threadIdx.x;
    if (e < NE) atomicAdd(&g_cnt[dst[e]], 1);
}
__global__ void k_dis() {
    int i = blockIdx.x * blockDim.x + threadIdx.x;
    if (i < NN) g_dis[i] = rsqrtf((float)g_cnt[i]);
}
__global__ void k_scan1() {
    __shared__ int s[1024];
    int i = blockIdx.x * 1024 + threadIdx.x;
    int v = (i < NN) ? g_cnt[i] : 0;
    s[threadIdx.x] = v;
    __syncthreads();
    for (int d = 1; d < 1024; d <<= 1) {
        int t = (threadIdx.x >= d) ? s[threadIdx.x - d] : 0;
        __syncthreads();
        s[threadIdx.x] += t;
        __syncthreads();
    }
    if (i < NN) g_rowptr[i + 1] = s[threadIdx.x];
    if (threadIdx.x == 1023) g_bsums[blockIdx.x] = s[1023];
}
__global__ void k_scan2(int nb) {
    __shared__ int s[128];
    int v = (threadIdx.x < nb) ? g_bsums[threadIdx.x] : 0;
    s[threadIdx.x] = v;
    __syncthreads();
    for (int d = 1; d < 128; d <<= 1) {
        int t = (threadIdx.x >= d) ? s[threadIdx.x - d] : 0;
        __syncthreads();
        s[threadIdx.x] += t;
        __syncthreads();
    }
    if (threadIdx.x < nb) g_bsums[threadIdx.x] = s[threadIdx.x] - v;
}
__global__ void k_scan3() {
    int i = blockIdx.x * 1024 + threadIdx.x;
    if (i < NN) g_rowptr[i + 1] += g_bsums[blockIdx.x];
    if (i == 0) g_rowptr[0] = 0;
}
__global__ void k_fill_init() {
    int i = blockIdx.x * blockDim.x + threadIdx.x;
    if (i < NN) g_fill[i] = g_rowptr[i];
}
__global__ void k_self() {
    int i = blockIdx.x * blockDim.x + threadIdx.x;
    if (i < NN) {
        int p = atomicAdd(&g_fill[i], 1);
        float d = g_dis[i];
        g_entries[p] = make_int2(i, __float_as_int(d * d));
    }
}
__global__ void k_edges(const int* __restrict__ src, const int* __restrict__ dst) {
    int e = blockIdx.x * blockDim.x + threadIdx.x;
    if (e < NE) {
        int s = src[e], d = dst[e];
        int p = atomicAdd(&g_fill[d], 1);
        g_entries[p] = make_int2(s, __float_as_int(g_dis[s] * g_dis[d]));
    }
}

// ---------------- scalar aggregation (C=3) ----------------
template <int C, int SUB, int ACT, bool BIAS>
__global__ void k_agg(const float* __restrict__ in, const float* __restrict__ bias,
                      float* __restrict__ out) {
    const int nodesPerWarp = 32 / SUB;
    int gwarp = (blockIdx.x * blockDim.x + threadIdx.x) >> 5;
    int lane = threadIdx.x & 31;
    int node = gwarp * nodesPerWarp + lane / SUB;
    int cl = lane % SUB;
    if (node >= NN) return;
    int p0 = g_rowptr[node], p1 = g_rowptr[node + 1];
    constexpr int NACC = (C + SUB - 1) / SUB;
    float acc[NACC];
#pragma unroll
    for (int j = 0; j < NACC; j++) acc[j] = 0.f;
    for (int p = p0; p < p1; p++) {
        int2 e = __ldg(&g_entries[p]);
        float w = __int_as_float(e.y);
        const float* fp = in + (long)e.x * C;
#pragma unroll
        for (int j = 0; j < NACC; j++) {
            int c = cl + j * SUB;
            if (c < C) acc[j] = fmaf(w, __ldg(fp + c), acc[j]);
        }
    }
#pragma unroll
    for (int j = 0; j < NACC; j++) {
        int c = cl + j * SUB;
        if (c < C) {
            float v = acc[j];
            if (BIAS) v += bias[c];
            if (ACT == 1) v = fmaxf(v, 0.f);
            if (ACT == 2) v = tanhf(v);
            out[(long)node * C + c] = v;
        }
    }
}

// ---------------- vectorized aggregation (C % 4 == 0) ----------------
// SUB lanes per node, NV = C/4 active vector lanes per node.
template <int C, int SUB, int ACT, bool BIAS>
__global__ void k_aggv(const float* __restrict__ in, const float* __restrict__ bias,
                       float* __restrict__ out) {
    constexpr int NV = C / 4;
    static_assert(NV <= SUB, "SUB too small");
    const int nodesPerWarp = 32 / SUB;
    int gwarp = (blockIdx.x * blockDim.x + threadIdx.x) >> 5;
    int lane = threadIdx.x & 31;
    int node = gwarp * nodesPerWarp + lane / SUB;
    int vl = lane % SUB;
    if (node >= NN) return;
    int p0 = g_rowptr[node], p1 = g_rowptr[node + 1];
    float4 acc = make_float4(0.f, 0.f, 0.f, 0.f);
    bool active = (vl < NV);
    for (int p = p0; p < p1; p++) {
        int2 e = __ldg(&g_entries[p]);
        float w = __int_as_float(e.y);
        if (active) {
            float4 v = __ldg((const float4*)(in + (long)e.x * C) + vl);
            acc.x = fmaf(w, v.x, acc.x);
            acc.y = fmaf(w, v.y, acc.y);
            acc.z = fmaf(w, v.z, acc.z);
            acc.w = fmaf(w, v.w, acc.w);
        }
    }
    if (active) {
        if (BIAS) {
            float4 bv = __ldg((const float4*)bias + vl);
            acc.x += bv.x; acc.y += bv.y; acc.z += bv.z; acc.w += bv.w;
        }
        if (ACT == 1) {
            acc.x = fmaxf(acc.x, 0.f); acc.y = fmaxf(acc.y, 0.f);
            acc.z = fmaxf(acc.z, 0.f); acc.w = fmaxf(acc.w, 0.f);
        }
        *((float4*)(out + (long)node * C) + vl) = acc;
    }
}

// ---------------- SIMT GEMM (small / memory-bound layers) ----------------
#define BMS 64
#define BNS 64
#define BKS 16
#define TMS 4
#define TNS 4
__global__ void __launch_bounds__(256)
k_gemm(const float* __restrict__ A, const float* __restrict__ W,
       const float* __restrict__ bias, float* __restrict__ out,
       int M, int K, int Nc, int act, int useBias) {
    __shared__ float sA[BKS][BMS + 1];
    __shared__ float sW[BKS][BNS];
    int tx = threadIdx.x % 16, ty = threadIdx.x / 16;
    int row0 = blockIdx.y * BMS, col0 = blockIdx.x * BNS;
    float acc[TMS][TNS] = {};
    for (int k0 = 0; k0 < K; k0 += BKS) {
        for (int i = threadIdx.x; i < BMS * BKS; i += 256) {
            int kk = i % BKS, m = i / BKS;
            int gm = row0 + m, gk = k0 + kk;
            sA[kk][m] = (gm < M && gk < K) ? A[(long)gm * K + gk] : 0.f;
        }
        for (int i = threadIdx.x; i < BKS * BNS; i += 256) {
            int n = i % BNS, kk = i / BNS;
            int gk = k0 + kk, gn = col0 + n;
            sW[kk][n] = (gk < K && gn < Nc) ? W[gk * Nc + gn] : 0.f;
        }
        __syncthreads();
#pragma unroll
        for (int kk = 0; kk < BKS; kk++) {
            float a[TMS];
#pragma unroll
            for (int i = 0; i < TMS; i++) a[i] = sA[kk][ty * TMS + i];
            float4 w4 = *(const float4*)&sW[kk][tx * TNS];
            float w[TNS] = {w4.x, w4.y, w4.z, w4.w};
#pragma unroll
            for (int i = 0; i < TMS; i++)
#pragma unroll
                for (int j = 0; j < TNS; j++) acc[i][j] = fmaf(a[i], w[j], acc[i][j]);
        }
        __syncthreads();
    }
#pragma unroll
    for (int i = 0; i < TMS; i++) {
        int gm = row0 + ty * TMS + i;
        if (gm >= M) continue;
#pragma unroll
        for (int j = 0; j < TNS; j++) {
            int gn = col0 + tx * TNS + j;
            if (gn >= Nc) continue;
            float v = acc[i][j];
            if (useBias) v += bias[gn];
            if (act == 1) v = fmaxf(v, 0.f);
            else if (act == 2) v = tanhf(v);
            out[(long)gm * Nc + gn] = v;
        }
    }
}

// ---------------- 3xTF32 tensor-core GEMM ----------------
// out[M,Nc] = act(A[M,K] @ W[K,Nc] + bias), full fp32 accuracy via hi/lo split.
// Block tile 128x80, BK=16, 256 threads = 8 warps as 4(m) x 2(n).
__device__ __forceinline__ uint32_t f2tf32(float x) {
    uint32_t r;
    asm("cvt.rna.tf32.f32 %0, %1;" : "=r"(r) : "f"(x));
    return r;
}
__device__ __forceinline__ void mma_tf32(float* c, uint32_t a0, uint32_t a1,
                                         uint32_t a2, uint32_t a3,
                                         uint32_t b0, uint32_t b1) {
    asm volatile(
        "mma.sync.aligned.m16n8k8.row.col.f32.tf32.tf32.f32 "
        "{%0,%1,%2,%3}, {%4,%5,%6,%7}, {%8,%9}, {%0,%1,%2,%3};\n"
        : "+f"(c[0]), "+f"(c[1]), "+f"(c[2]), "+f"(c[3])
        : "r"(a0), "r"(a1), "r"(a2), "r"(a3), "r"(b0), "r"(b1));
}

#define TBM 128
#define TBN 80
#define TBK 16
#define SA_STR 20   // conflict-free for fragment pattern
#define SB_STR 88   // conflict-free for fragment pattern

template <int ACT, bool BIAS>
__global__ void __launch_bounds__(256)
k_gemm_tf32(const float* __restrict__ A, const float* __restrict__ W,
            const float* __restrict__ bias, float* __restrict__ out,
            int M, int K, int Nc) {
    __shared__ uint32_t sAh[TBM * SA_STR];
    __shared__ uint32_t sAl[TBM * SA_STR];
    __shared__ uint32_t sBh[TBK * SB_STR];
    __shared__ uint32_t sBl[TBK * SB_STR];

    int tid = threadIdx.x;
    int wid = tid >> 5;
    int lane = tid & 31;
    int g = lane >> 2;       // groupID
    int t = lane & 3;        // threadID_in_group
    int wm = wid & 3;        // 0..3 -> 32 rows each
    int wn = wid >> 2;       // 0..1 -> 40 cols each
    int row0 = blockIdx.y * TBM;
    int col0 = blockIdx.x * TBN;

    float acc[2][5][4];
#pragma unroll
    for (int i = 0; i < 2; i++)
#pragma unroll
        for (int j = 0; j < 5; j++)
#pragma unroll
            for (int q = 0; q < 4; q++) acc[i][j][q] = 0.f;

    for (int k0 = 0; k0 < K; k0 += TBK) {
        // load A tile: 128x16 elems, 8 per thread
#pragma unroll
        for (int it = 0; it < 8; it++) {
            int idx = tid + it * 256;
            int m = idx >> 4, kk = idx & 15;
            int gm = row0 + m, gk = k0 + kk;
            float v = (gm < M && gk < K) ? A[(long)gm * K + gk] : 0.f;
            uint32_t hi = f2tf32(v);
            float rest = v - __uint_as_float(hi);
            sAh[m * SA_STR + kk] = hi;
            sAl[m * SA_STR + kk] = f2tf32(rest);
        }
        // load B tile: 16x80 elems, 5 per thread
#pragma unroll
        for (int it = 0; it < 5; it++) {
            int idx = tid + it * 256;
            int kk = idx / 80, n = idx - kk * 80;
            int gk = k0 + kk, gn = col0 + n;
            float v = (gk < K && gn < Nc) ? W[(long)gk * Nc + gn] : 0.f;
            uint32_t hi = f2tf32(v);
            float rest = v - __uint_as_float(hi);
            sBh[kk * SB_STR + n] = hi;
            sBl[kk * SB_STR + n] = f2tf32(rest);
        }
        __syncthreads();

#pragma unroll
        for (int ks = 0; ks < TBK; ks += 8) {
            uint32_t ah[2][4], al[2][4];
#pragma unroll
            for (int i = 0; i < 2; i++) {
                int r0 = wm * 32 + i * 16 + g;
                ah[i][0] = sAh[r0 * SA_STR + ks + t];
                ah[i][1] = sAh[(r0 + 8) * SA_STR + ks + t];
                ah[i][2] = sAh[r0 * SA_STR + ks + t + 4];
                ah[i][3] = sAh[(r0 + 8) * SA_STR + ks + t + 4];
                al[i][0] = sAl[r0 * SA_STR + ks + t];
                al[i][1] = sAl[(r0 + 8) * SA_STR + ks + t];
                al[i][2] = sAl[r0 * SA_STR + ks + t + 4];
                al[i][3] = sAl[(r0 + 8) * SA_STR + ks + t + 4];
            }
#pragma unroll
            for (int j = 0; j < 5; j++) {
                int c = wn * 40 + j * 8 + g;
                uint32_t bh0 = sBh[(ks + t) * SB_STR + c];
                uint32_t bh1 = sBh[(ks + t + 4) * SB_STR + c];
                uint32_t bl0 = sBl[(ks + t) * SB_STR + c];
                uint32_t bl1 = sBl[(ks + t + 4) * SB_STR + c];
#pragma unroll
                for (int i = 0; i < 2; i++) {
                    mma_tf32(acc[i][j], ah[i][0], ah[i][1], ah[i][2], ah[i][3], bh0, bh1);
                    mma_tf32(acc[i][j], ah[i][0], ah[i][1], ah[i][2], ah[i][3], bl0, bl1);
                    mma_tf32(acc[i][j], al[i][0], al[i][1], al[i][2], al[i][3], bh0, bh1);
                }
            }
        }
        __syncthreads();
    }

    // epilogue: c0:(r, 2t) c1:(r, 2t+1) c2:(r+8, 2t) c3:(r+8, 2t+1)
#pragma unroll
    for (int i = 0; i < 2; i++) {
        int rbase = row0 + wm * 32 + i * 16 + g;
#pragma unroll
        for (int j = 0; j < 5; j++) {
            int cbase = col0 + wn * 40 + j * 8 + t * 2;
#pragma unroll
            for (int q = 0; q < 4; q++) {
                int gm = rbase + ((q >= 2) ? 8 : 0);
                int gn = cbase + (q & 1);
                if (gm < M && gn < Nc) {
                    float v = acc[i][j][q];
                    if (BIAS) v += bias[gn];
                    if (ACT == 1) v = fmaxf(v, 0.f);
                    out[(long)gm * Nc + gn] = v;
                }
            }
        }
    }
}

// ---------------- fused dense chain: 20 ->10(relu) ->3 ->10(relu) ->20(relu) ----------------
__global__ void __launch_bounds__(256)
k_chain(const float* __restrict__ in, float* __restrict__ out,
        const float* __restrict__ w1, const float* __restrict__ b1,   // 20x10
        const float* __restrict__ w2, const float* __restrict__ b2,   // 10x3
        const float* __restrict__ w3, const float* __restrict__ b3,   // 3x10
        const float* __restrict__ w4, const float* __restrict__ b4) { // 10x20
    __shared__ float sw1[200], sb1[10], sw2[30], sb2[3], sw3[30], sb3[10], sw4[200], sb4[20];
    int tid = threadIdx.x;
    for (int i = tid; i < 200; i += 256) sw1[i] = w1[i];
    for (int i = tid; i < 10; i += 256) sb1[i] = b1[i];
    for (int i = tid; i < 30; i += 256) sw2[i] = w2[i];
    for (int i = tid; i < 3; i += 256) sb2[i] = b2[i];
    for (int i = tid; i < 30; i += 256) sw3[i] = w3[i];
    for (int i = tid; i < 10; i += 256) sb3[i] = b3[i];
    for (int i = tid; i < 200; i += 256) sw4[i] = w4[i];
    for (int i = tid; i < 20; i += 256) sb4[i] = b4[i];
    __syncthreads();

    int n = blockIdx.x * blockDim.x + tid;
    if (n >= NN) return;
    float h0[20];
    const float4* ip = (const float4*)(in + (long)n * 20);
#pragma unroll
    for (int i = 0; i < 5; i++) {
        float4 v = __ldg(ip + i);
        h0[i * 4 + 0] = v.x; h0[i * 4 + 1] = v.y; h0[i * 4 + 2] = v.z; h0[i * 4 + 3] = v.w;
    }
    float h1[10];
#pragma unroll
    for (int j = 0; j < 10; j++) {
        float s = sb1[j];
#pragma unroll
        for (int i = 0; i < 20; i++) s = fmaf(h0[i], sw1[i * 10 + j], s);
        h1[j] = fmaxf(s, 0.f);
    }
    float z[3];
#pragma unroll
    for (int j = 0; j < 3; j++) {
        float s = sb2[j];
#pragma unroll
        for (int i = 0; i < 10; i++) s = fmaf(h1[i], sw2[i * 3 + j], s);
        z[j] = s;
    }
    float h2[10];
#pragma unroll
    for (int j = 0; j < 10; j++) {
        float s = sb3[j];
#pragma unroll
        for (int i = 0; i < 3; i++) s = fmaf(z[i], sw3[i * 10 + j], s);
        h2[j] = fmaxf(s, 0.f);
    }
    float* op = out + (long)n * 20;
#pragma unroll
    for (int j = 0; j < 20; j++) {
        float s = sb4[j];
#pragma unroll
        for (int i = 0; i < 10; i++) s = fmaf(h2[i], sw4[i * 20 + j], s);
        op[j] = fmaxf(s, 0.f);
    }
}

// ---------------- driver ----------------
static void gemm_s(const float* A, const float* W, const float* b, float* o,
                   int K, int Nc, int act, int useBias) {
    dim3 g(cdiv(Nc, BNS), cdiv(NN, BMS));
    k_gemm<<<g, 256>>>(A, W, b, o, NN, K, Nc, act, useBias);
}
template <int ACT, bool BIAS>
static void gemm_t(const float* A, const float* W, const float* b, float* o, int K, int Nc) {
    dim3 g(cdiv(Nc, TBN), cdiv(NN, TBM));
    k_gemm_tf32<ACT, BIAS><<<g, 256>>>(A, W, b, o, NN, K, Nc);
}

extern "C" void kernel_launch(void* const* d_in, const int* in_sizes, int n_in,
                              void* d_out, int out_size) {
    const float* x = (const float*)d_in[0];
    const int* ei = (const int*)d_in[1];
    const int* src = ei;
    const int* dst = ei + NE;
    const float* W[12];
    const float* B[12];
    for (int i = 0; i < 12; i++) {
        W[i] = (const float*)d_in[2 + 2 * i];
        B[i] = (const float*)d_in[3 + 2 * i];
    }
    float* bufA; cudaGetSymbolAddress((void**)&bufA, g_bufA);
    float* bufB; cudaGetSymbolAddress((void**)&bufB, g_bufB);
    float* outp = (float*)d_out;

    const int NB = cdiv(NN, 1024);
    // CSR build
    k_init_cnt<<<cdiv(NN, 256), 256>>>();
    k_count<<<cdiv(NE, 256), 256>>>(dst);
    k_dis<<<cdiv(NN, 256), 256>>>();
    k_scan1<<<NB, 1024>>>();
    k_scan2<<<1, 128>>>(NB);
    k_scan3<<<NB, 1024>>>();
    k_fill_init<<<cdiv(NN, 256), 256>>>();
    k_self<<<cdiv(NN, 256), 256>>>();
    k_edges<<<cdiv(NE, 256), 256>>>(src, dst);

    const int TPB = 256;
    int blocks32 = cdiv(NN * 32, TPB);                 // SUB=32 (1 node/warp)
    int blocks16 = cdiv(cdiv(NN, 2) * 32, TPB);        // SUB=16
    int blocks8  = cdiv(cdiv(NN, 4) * 32, TPB);        // SUB=8
    int blocks4  = cdiv(cdiv(NN, 8) * 32, TPB);        // SUB=4 scalar C=3

    // encoder
    k_agg<3, 4, 0, false><<<blocks4, TPB>>>(x, nullptr, bufA);          // agg(x) C=3
    gemm_s(bufA, W[0], B[0], bufB, 3, 160, 1, 1);                       // eg1 relu(a@W+b)
    gemm_t<0, false>(bufB, W[1], nullptr, bufA, 160, 80);               // eg2 matmul
    k_aggv<80, 32, 1, true><<<blocks32, TPB>>>(bufA, B[1], bufB);       // eg2 agg+b+relu
    gemm_t<0, false>(bufB, W[2], nullptr, bufA, 80, 40);                // eg3 matmul
    k_aggv<40, 16, 1, true><<<blocks16, TPB>>>(bufA, B[2], bufB);       // eg3 agg+b+relu
    gemm_s(bufB, W[3], nullptr, bufA, 40, 20, 0, 0);                    // eg4 matmul
    k_aggv<20, 8, 1, true><<<blocks8, TPB>>>(bufA, B[3], bufB);         // eg4 agg+b+relu
    // latent dense chain (el1,el2,dl1,dl2) fused
    k_chain<<<cdiv(NN, 256), 256>>>(bufB, bufA, W[4], B[4], W[5], B[5], W[6], B[6], W[7], B[7]);
    // decoder
    k_aggv<20, 8, 0, false><<<blocks8, TPB>>>(bufA, nullptr, bufB);     // dg1 agg
    gemm_s(bufB, W[8], B[8], bufA, 20, 40, 1, 1);                       // dg1 relu(a@W+b)
    k_aggv<40, 16, 0, false><<<blocks16, TPB>>>(bufA, nullptr, bufB);   // dg2 agg
    gemm_t<1, true>(bufB, W[9], B[9], bufA, 40, 80);                    // dg2 relu(a@W+b)
    k_aggv<80, 32, 0, false><<<blocks32, TPB>>>(bufA, nullptr, bufB);   // dg3 agg
    gemm_t<1, true>(bufB, W[10], B[10], bufA, 80, 160);                 // dg3 relu(a@W+b)
    gemm_s(bufA, W[11], nullptr, bufB, 160, 3, 0, 0);                   // dg4 matmul
    k_agg<3, 4, 2, true><<<blocks4, TPB>>>(bufB, B[11], outp);          // dg4 agg+b+tanh
}

// round 3
// speedup vs baseline: 1.2876x; 1.0638x over previous
#include <cuda_runtime.h>
#include <cuda_bf16.h>
#include <cstdint>

#define NN 100000
#define NE 1600000
#define NTOT (NE + NN)

// ---------------- scratch (device globals: allocation-free) ----------------
__device__ float g_bufA[NN * 160];
__device__ float g_bufB[NN * 160];
__device__ int   g_cnt[NN];
__device__ float g_dis[NN];
__device__ int   g_rowptr[NN + 1];
__device__ int   g_fill[NN];
__device__ int2  g_entries[NTOT];   // {src_node, float_bits(norm)} sorted by dst
__device__ int   g_bsums[128];

static inline int cdiv(int a, int b) { return (a + b - 1) / b; }

// ---------------- CSR build ----------------
__global__ void k_init_cnt() {
    int i = blockIdx.x * blockDim.x + threadIdx.x;
    if (i < NN) g_cnt[i] = 1;   // self-loop
}
__global__ void k_count(const int* __restrict__ dst) {
    int e = blockIdx.x * blockDim.x + threadIdx.x;
    if (e < NE) atomicAdd(&g_cnt[dst[e]], 1);
}
__global__ void k_scan1() {   // also computes g_dis
    __shared__ int s[1024];
    int i = blockIdx.x * 1024 + threadIdx.x;
    int v = (i < NN) ? g_cnt[i] : 0;
    if (i < NN) g_dis[i] = rsqrtf((float)v);
    s[threadIdx.x] = v;
    __syncthreads();
    for (int d = 1; d < 1024; d <<= 1) {
        int t = (threadIdx.x >= d) ? s[threadIdx.x - d] : 0;
        __syncthreads();
        s[threadIdx.x] += t;
        __syncthreads();
    }
    if (i < NN) g_rowptr[i + 1] = s[threadIdx.x];
    if (threadIdx.x == 1023) g_bsums[blockIdx.x] = s[1023];
}
__global__ void k_scan2(int nb) {
    __shared__ int s[128];
    int v = (threadIdx.x < nb) ? g_bsums[threadIdx.x] : 0;
    s[threadIdx.x] = v;
    __syncthreads();
    for (int d = 1; d < 128; d <<= 1) {
        int t = (threadIdx.x >= d) ? s[threadIdx.x - d] : 0;
        __syncthreads();
        s[threadIdx.x] += t;
        __syncthreads();
    }
    if (threadIdx.x < nb) g_bsums[threadIdx.x] = s[threadIdx.x] - v;
}
__global__ void k_scan3() {
    int i = blockIdx.x * 1024 + threadIdx.x;
    if (i < NN) g_rowptr[i + 1] += g_bsums[blockIdx.x];
    if (i == 0) g_rowptr[0] = 0;
}
__global__ void k_self() {   // self-loop entry + init fill cursor
    int i = blockIdx.x * blockDim.x + threadIdx.x;
    if (i < NN) {
        int p = g_rowptr[i];
        float d = g_dis[i];
        g_entries[p] = make_int2(i, __float_as_int(d * d));
        g_fill[i] = p + 1;
    }
}
__global__ void k_edges(const int* __restrict__ src, const int* __restrict__ dst) {
    int e = blockIdx.x * blockDim.x + threadIdx.x;
    if (e < NE) {
        int s = src[e], d = dst[e];
        int p = atomicAdd(&g_fill[d], 1);
        g_entries[p] = make_int2(s, __float_as_int(g_dis[s] * g_dis[d]));
    }
}

// ---------------- scalar aggregation (C=3), unroll-4 ----------------
template <int ACT, bool BIAS>
__global__ void k_agg3(const float* __restrict__ in, const float* __restrict__ bias,
                       float* __restrict__ out) {
    int gwarp = (blockIdx.x * blockDim.x + threadIdx.x) >> 5;
    int lane = threadIdx.x & 31;
    int node = gwarp * 8 + lane / 4;
    int cl = lane & 3;
    if (node >= NN) return;
    int p0 = g_rowptr[node], p1 = g_rowptr[node + 1];
    float acc = 0.f;
    bool act3 = (cl < 3);
    int p = p0;
    for (; p + 4 <= p1; p += 4) {
        int2 e0 = __ldg(&g_entries[p]);
        int2 e1 = __ldg(&g_entries[p + 1]);
        int2 e2 = __ldg(&g_entries[p + 2]);
        int2 e3 = __ldg(&g_entries[p + 3]);
        if (act3) {
            float v0 = __ldg(in + (long)e0.x * 3 + cl);
            float v1 = __ldg(in + (long)e1.x * 3 + cl);
            float v2 = __ldg(in + (long)e2.x * 3 + cl);
            float v3 = __ldg(in + (long)e3.x * 3 + cl);
            acc = fmaf(__int_as_float(e0.y), v0, acc);
            acc = fmaf(__int_as_float(e1.y), v1, acc);
            acc = fmaf(__int_as_float(e2.y), v2, acc);
            acc = fmaf(__int_as_float(e3.y), v3, acc);
        }
    }
    for (; p < p1; p++) {
        int2 e = __ldg(&g_entries[p]);
        if (act3) {
            float v = __ldg(in + (long)e.x * 3 + cl);
            acc = fmaf(__int_as_float(e.y), v, acc);
        }
    }
    if (act3) {
        float v = acc;
        if (BIAS) v += bias[cl];
        if (ACT == 1) v = fmaxf(v, 0.f);
        if (ACT == 2) v = tanhf(v);
        out[(long)node * 3 + cl] = v;
    }
}

// ---------------- vectorized aggregation (C % 4 == 0), unroll-4 ----------------
template <int C, int SUB, int ACT, bool BIAS>
__global__ void k_aggv(const float* __restrict__ in, const float* __restrict__ bias,
                       float* __restrict__ out) {
    constexpr int NV = C / 4;
    static_assert(NV <= SUB, "SUB too small");
    const int nodesPerWarp = 32 / SUB;
    int gwarp = (blockIdx.x * blockDim.x + threadIdx.x) >> 5;
    int lane = threadIdx.x & 31;
    int node = gwarp * nodesPerWarp + lane / SUB;
    int vl = lane % SUB;
    if (node >= NN) return;
    int p0 = g_rowptr[node], p1 = g_rowptr[node + 1];
    float4 acc = make_float4(0.f, 0.f, 0.f, 0.f);
    bool active = (vl < NV);
    int p = p0;
    for (; p + 4 <= p1; p += 4) {
        int2 e0 = __ldg(&g_entries[p]);
        int2 e1 = __ldg(&g_entries[p + 1]);
        int2 e2 = __ldg(&g_entries[p + 2]);
        int2 e3 = __ldg(&g_entries[p + 3]);
        if (active) {
            float4 v0 = __ldg((const float4*)(in + (long)e0.x * C) + vl);
            float4 v1 = __ldg((const float4*)(in + (long)e1.x * C) + vl);
            float4 v2 = __ldg((const float4*)(in + (long)e2.x * C) + vl);
            float4 v3 = __ldg((const float4*)(in + (long)e3.x * C) + vl);
            float w0 = __int_as_float(e0.y), w1 = __int_as_float(e1.y);
            float w2 = __int_as_float(e2.y), w3 = __int_as_float(e3.y);
            acc.x = fmaf(w0, v0.x, acc.x); acc.y = fmaf(w0, v0.y, acc.y);
            acc.z = fmaf(w0, v0.z, acc.z); acc.w = fmaf(w0, v0.w, acc.w);
            acc.x = fmaf(w1, v1.x, acc.x); acc.y = fmaf(w1, v1.y, acc.y);
            acc.z = fmaf(w1, v1.z, acc.z); acc.w = fmaf(w1, v1.w, acc.w);
            acc.x = fmaf(w2, v2.x, acc.x); acc.y = fmaf(w2, v2.y, acc.y);
            acc.z = fmaf(w2, v2.z, acc.z); acc.w = fmaf(w2, v2.w, acc.w);
            acc.x = fmaf(w3, v3.x, acc.x); acc.y = fmaf(w3, v3.y, acc.y);
            acc.z = fmaf(w3, v3.z, acc.z); acc.w = fmaf(w3, v3.w, acc.w);
        }
    }
    for (; p < p1; p++) {
        int2 e = __ldg(&g_entries[p]);
        if (active) {
            float w = __int_as_float(e.y);
            float4 v = __ldg((const float4*)(in + (long)e.x * C) + vl);
            acc.x = fmaf(w, v.x, acc.x); acc.y = fmaf(w, v.y, acc.y);
            acc.z = fmaf(w, v.z, acc.z); acc.w = fmaf(w, v.w, acc.w);
        }
    }
    if (active) {
        if (BIAS) {
            float4 bv = __ldg((const float4*)bias + vl);
            acc.x += bv.x; acc.y += bv.y; acc.z += bv.z; acc.w += bv.w;
        }
        if (ACT == 1) {
            acc.x = fmaxf(acc.x, 0.f); acc.y = fmaxf(acc.y, 0.f);
            acc.z = fmaxf(acc.z, 0.f); acc.w = fmaxf(acc.w, 0.f);
        }
        *((float4*)(out + (long)node * C) + vl) = acc;
    }
}

// ---------------- fused eg1: out = relu(agg(x, C=3) @ W(3x160) + b) ----------------
__global__ void __launch_bounds__(256)
k_eg1(const float* __restrict__ x, const float* __restrict__ W,
      const float* __restrict__ Bb, float* __restrict__ out) {
    __shared__ float sW[480];
    __shared__ float sB[160];
    for (int i = threadIdx.x; i < 480; i += 256) sW[i] = W[i];
    for (int i = threadIdx.x; i < 160; i += 256) sB[i] = Bb[i];
    __syncthreads();
    int gwarp = (blockIdx.x * blockDim.x + threadIdx.x) >> 5;
    int lane = threadIdx.x & 31;
    int nodeBase = gwarp * 8;
    int node = nodeBase + lane / 4;
    int cl = lane & 3;
    float acc = 0.f;
    if (node < NN) {
        int p0 = g_rowptr[node], p1 = g_rowptr[node + 1];
        bool act3 = (cl < 3);
        int p = p0;
        for (; p + 4 <= p1; p += 4) {
            int2 e0 = __ldg(&g_entries[p]);
            int2 e1 = __ldg(&g_entries[p + 1]);
            int2 e2 = __ldg(&g_entries[p + 2]);
            int2 e3 = __ldg(&g_entries[p + 3]);
            if (act3) {
                float v0 = __ldg(x + (long)e0.x * 3 + cl);
                float v1 = __ldg(x + (long)e1.x * 3 + cl);
                float v2 = __ldg(x + (long)e2.x * 3 + cl);
                float v3 = __ldg(x + (long)e3.x * 3 + cl);
                acc = fmaf(__int_as_float(e0.y), v0, acc);
                acc = fmaf(__int_as_float(e1.y), v1, acc);
                acc = fmaf(__int_as_float(e2.y), v2, acc);
                acc = fmaf(__int_as_float(e3.y), v3, acc);
            }
        }
        for (; p < p1; p++) {
            int2 e = __ldg(&g_entries[p]);
            if (act3) {
                float v = __ldg(x + (long)e.x * 3 + cl);
                acc = fmaf(__int_as_float(e.y), v, acc);
            }
        }
    }
    // expansion: 8 nodes per warp, warp-cooperative 160-wide output
#pragma unroll
    for (int j = 0; j < 8; j++) {
        int n2 = nodeBase + j;
        float a0 = __shfl_sync(0xffffffffu, acc, j * 4 + 0);
        float a1 = __shfl_sync(0xffffffffu, acc, j * 4 + 1);
        float a2 = __shfl_sync(0xffffffffu, acc, j * 4 + 2);
        if (n2 >= NN) break;
        float* op = out + (long)n2 * 160;
#pragma unroll
        for (int c0 = 0; c0 < 160; c0 += 32) {
            int c = c0 + lane;
            float v = sB[c];
            v = fmaf(a0, sW[c], v);
            v = fmaf(a1, sW[160 + c], v);
            v = fmaf(a2, sW[320 + c], v);
            op[c] = fmaxf(v, 0.f);
        }
    }
}

// ---------------- SIMT GEMM (small / memory-bound layers) ----------------
#define BMS 64
#define BNS 64
#define BKS 16
#define TMS 4
#define TNS 4
__global__ void __launch_bounds__(256)
k_gemm(const float* __restrict__ A, const float* __restrict__ W,
       const float* __restrict__ bias, float* __restrict__ out,
       int M, int K, int Nc, int act, int useBias) {
    __shared__ float sA[BKS][BMS + 1];
    __shared__ float sW[BKS][BNS];
    int tx = threadIdx.x % 16, ty = threadIdx.x / 16;
    int row0 = blockIdx.y * BMS, col0 = blockIdx.x * BNS;
    float acc[TMS][TNS] = {};
    for (int k0 = 0; k0 < K; k0 += BKS) {
        for (int i = threadIdx.x; i < BMS * BKS; i += 256) {
            int kk = i % BKS, m = i / BKS;
            int gm = row0 + m, gk = k0 + kk;
            sA[kk][m] = (gm < M && gk < K) ? A[(long)gm * K + gk] : 0.f;
        }
        for (int i = threadIdx.x; i < BKS * BNS; i += 256) {
            int n = i % BNS, kk = i / BNS;
            int gk = k0 + kk, gn = col0 + n;
            sW[kk][n] = (gk < K && gn < Nc) ? W[gk * Nc + gn] : 0.f;
        }
        __syncthreads();
#pragma unroll
        for (int kk = 0; kk < BKS; kk++) {
            float a[TMS];
#pragma unroll
            for (int i = 0; i < TMS; i++) a[i] = sA[kk][ty * TMS + i];
            float4 w4 = *(const float4*)&sW[kk][tx * TNS];
            float w[TNS] = {w4.x, w4.y, w4.z, w4.w};
#pragma unroll
            for (int i = 0; i < TMS; i++)
#pragma unroll
                for (int j = 0; j < TNS; j++) acc[i][j] = fmaf(a[i], w[j], acc[i][j]);
        }
        __syncthreads();
    }
#pragma unroll
    for (int i = 0; i < TMS; i++) {
        int gm = row0 + ty * TMS + i;
        if (gm >= M) continue;
#pragma unroll
        for (int j = 0; j < TNS; j++) {
            int gn = col0 + tx * TNS + j;
            if (gn >= Nc) continue;
            float v = acc[i][j];
            if (useBias) v += bias[gn];
            if (act == 1) v = fmaxf(v, 0.f);
            else if (act == 2) v = tanhf(v);
            out[(long)gm * Nc + gn] = v;
        }
    }
}

// ---------------- 3xTF32 tensor-core GEMM ----------------
__device__ __forceinline__ uint32_t f2tf32(float x) {
    uint32_t r;
    asm("cvt.rna.tf32.f32 %0, %1;" : "=r"(r) : "f"(x));
    return r;
}
__device__ __forceinline__ void mma_tf32(float* c, uint32_t a0, uint32_t a1,
                                         uint32_t a2, uint32_t a3,
                                         uint32_t b0, uint32_t b1) {
    asm volatile(
        "mma.sync.aligned.m16n8k8.row.col.f32.tf32.tf32.f32 "
        "{%0,%1,%2,%3}, {%4,%5,%6,%7}, {%8,%9}, {%0,%1,%2,%3};\n"
        : "+f"(c[0]), "+f"(c[1]), "+f"(c[2]), "+f"(c[3])
        : "r"(a0), "r"(a1), "r"(a2), "r"(a3), "r"(b0), "r"(b1));
}

#define TBM 128
#define TBN 80
#define TBK 16
#define SA_STR 20
#define SB_STR 88

template <int ACT, bool BIAS>
__global__ void __launch_bounds__(256)
k_gemm_tf32(const float* __restrict__ A, const float* __restrict__ W,
            const float* __restrict__ bias, float* __restrict__ out,
            int M, int K, int Nc) {
    __shared__ uint32_t sAh[TBM * SA_STR];
    __shared__ uint32_t sAl[TBM * SA_STR];
    __shared__ uint32_t sBh[TBK * SB_STR];
    __shared__ uint32_t sBl[TBK * SB_STR];

    int tid = threadIdx.x;
    int wid = tid >> 5;
    int lane = tid & 31;
    int g = lane >> 2;
    int t = lane & 3;
    int wm = wid & 3;
    int wn = wid >> 2;
    int row0 = blockIdx.y * TBM;
    int col0 = blockIdx.x * TBN;

    float acc[2][5][4];
#pragma unroll
    for (int i = 0; i < 2; i++)
#pragma unroll
        for (int j = 0; j < 5; j++)
#pragma unroll
            for (int q = 0; q < 4; q++) acc[i][j][q] = 0.f;

    for (int k0 = 0; k0 < K; k0 += TBK) {
#pragma unroll
        for (int it = 0; it < 8; it++) {
            int idx = tid + it * 256;
            int m = idx >> 4, kk = idx & 15;
            int gm = row0 + m, gk = k0 + kk;
            float v = (gm < M && gk < K) ? A[(long)gm * K + gk] : 0.f;
            uint32_t hi = f2tf32(v);
            float rest = v - __uint_as_float(hi);
            sAh[m * SA_STR + kk] = hi;
            sAl[m * SA_STR + kk] = f2tf32(rest);
        }
#pragma unroll
        for (int it = 0; it < 5; it++) {
            int idx = tid + it * 256;
            int kk = idx / 80, n = idx - kk * 80;
            int gk = k0 + kk, gn = col0 + n;
            float v = (gk < K && gn < Nc) ? W[(long)gk * Nc + gn] : 0.f;
            uint32_t hi = f2tf32(v);
            float rest = v - __uint_as_float(hi);
            sBh[kk * SB_STR + n] = hi;
            sBl[kk * SB_STR + n] = f2tf32(rest);
        }
        __syncthreads();

#pragma unroll
        for (int ks = 0; ks < TBK; ks += 8) {
            uint32_t ah[2][4], al[2][4];
#pragma unroll
            for (int i = 0; i < 2; i++) {
                int r0 = wm * 32 + i * 16 + g;
                ah[i][0] = sAh[r0 * SA_STR + ks + t];
                ah[i][1] = sAh[(r0 + 8) * SA_STR + ks + t];
                ah[i][2] = sAh[r0 * SA_STR + ks + t + 4];
                ah[i][3] = sAh[(r0 + 8) * SA_STR + ks + t + 4];
                al[i][0] = sAl[r0 * SA_STR + ks + t];
                al[i][1] = sAl[(r0 + 8) * SA_STR + ks + t];
                al[i][2] = sAl[r0 * SA_STR + ks + t + 4];
                al[i][3] = sAl[(r0 + 8) * SA_STR + ks + t + 4];
            }
#pragma unroll
            for (int j = 0; j < 5; j++) {
                int c = wn * 40 + j * 8 + g;
                uint32_t bh0 = sBh[(ks + t) * SB_STR + c];
                uint32_t bh1 = sBh[(ks + t + 4) * SB_STR + c];
                uint32_t bl0 = sBl[(ks + t) * SB_STR + c];
                uint32_t bl1 = sBl[(ks + t + 4) * SB_STR + c];
#pragma unroll
                for (int i = 0; i < 2; i++) {
                    mma_tf32(acc[i][j], ah[i][0], ah[i][1], ah[i][2], ah[i][3], bh0, bh1);
                    mma_tf32(acc[i][j], ah[i][0], ah[i][1], ah[i][2], ah[i][3], bl0, bl1);
                    mma_tf32(acc[i][j], al[i][0], al[i][1], al[i][2], al[i][3], bh0, bh1);
                }
            }
        }
        __syncthreads();
    }

#pragma unroll
    for (int i = 0; i < 2; i++) {
        int rbase = row0 + wm * 32 + i * 16 + g;
#pragma unroll
        for (int j = 0; j < 5; j++) {
            int cbase = col0 + wn * 40 + j * 8 + t * 2;
#pragma unroll
            for (int q = 0; q < 4; q++) {
                int gm = rbase + ((q >= 2) ? 8 : 0);
                int gn = cbase + (q & 1);
                if (gm < M && gn < Nc) {
                    float v = acc[i][j][q];
                    if (BIAS) v += bias[gn];
                    if (ACT == 1) v = fmaxf(v, 0.f);
                    out[(long)gm * Nc + gn] = v;
                }
            }
        }
    }
}

// ---------------- fused dense chain ----------------
__global__ void __launch_bounds__(256)
k_chain(const float* __restrict__ in, float* __restrict__ out,
        const float* __restrict__ w1, const float* __restrict__ b1,
        const float* __restrict__ w2, const float* __restrict__ b2,
        const float* __restrict__ w3, const float* __restrict__ b3,
        const float* __restrict__ w4, const float* __restrict__ b4) {
    __shared__ float sw1[200], sb1[10], sw2[30], sb2[3], sw3[30], sb3[10], sw4[200], sb4[20];
    int tid = threadIdx.x;
    for (int i = tid; i < 200; i += 256) sw1[i] = w1[i];
    for (int i = tid; i < 10; i += 256) sb1[i] = b1[i];
    for (int i = tid; i < 30; i += 256) sw2[i] = w2[i];
    for (int i = tid; i < 3; i += 256) sb2[i] = b2[i];
    for (int i = tid; i < 30; i += 256) sw3[i] = w3[i];
    for (int i = tid; i < 10; i += 256) sb3[i] = b3[i];
    for (int i = tid; i < 200; i += 256) sw4[i] = w4[i];
    for (int i = tid; i < 20; i += 256) sb4[i] = b4[i];
    __syncthreads();

    int n = blockIdx.x * blockDim.x + tid;
    if (n >= NN) return;
    float h0[20];
    const float4* ip = (const float4*)(in + (long)n * 20);
#pragma unroll
    for (int i = 0; i < 5; i++) {
        float4 v = __ldg(ip + i);
        h0[i * 4 + 0] = v.x; h0[i * 4 + 1] = v.y; h0[i * 4 + 2] = v.z; h0[i * 4 + 3] = v.w;
    }
    float h1[10];
#pragma unroll
    for (int j = 0; j < 10; j++) {
        float s = sb1[j];
#pragma unroll
        for (int i = 0; i < 20; i++) s = fmaf(h0[i], sw1[i * 10 + j], s);
        h1[j] = fmaxf(s, 0.f);
    }
    float z[3];
#pragma unroll
    for (int j = 0; j < 3; j++) {
        float s = sb2[j];
#pragma unroll
        for (int i = 0; i < 10; i++) s = fmaf(h1[i], sw2[i * 3 + j], s);
        z[j] = s;
    }
    float h2[10];
#pragma unroll
    for (int j = 0; j < 10; j++) {
        float s = sb3[j];
#pragma unroll
        for (int i = 0; i < 3; i++) s = fmaf(z[i], sw3[i * 10 + j], s);
        h2[j] = fmaxf(s, 0.f);
    }
    float* op = out + (long)n * 20;
#pragma unroll
    for (int j = 0; j < 20; j++) {
        float s = sb4[j];
#pragma unroll
        for (int i = 0; i < 10; i++) s = fmaf(h2[i], sw4[i * 20 + j], s);
        op[j] = fmaxf(s, 0.f);
    }
}

// ---------------- driver ----------------
static void gemm_s(const float* A, const float* W, const float* b, float* o,
                   int K, int Nc, int act, int useBias) {
    dim3 g(cdiv(Nc, BNS), cdiv(NN, BMS));
    k_gemm<<<g, 256>>>(A, W, b, o, NN, K, Nc, act, useBias);
}
template <int ACT, bool BIAS>
static void gemm_t(const float* A, const float* W, const float* b, float* o, int K, int Nc) {
    dim3 g(cdiv(Nc, TBN), cdiv(NN, TBM));
    k_gemm_tf32<ACT, BIAS><<<g, 256>>>(A, W, b, o, NN, K, Nc);
}

extern "C" void kernel_launch(void* const* d_in, const int* in_sizes, int n_in,
                              void* d_out, int out_size) {
    const float* x = (const float*)d_in[0];
    const int* ei = (const int*)d_in[1];
    const int* src = ei;
    const int* dst = ei + NE;
    const float* W[12];
    const float* B[12];
    for (int i = 0; i < 12; i++) {
        W[i] = (const float*)d_in[2 + 2 * i];
        B[i] = (const float*)d_in[3 + 2 * i];
    }
    float* bufA; cudaGetSymbolAddress((void**)&bufA, g_bufA);
    float* bufB; cudaGetSymbolAddress((void**)&bufB, g_bufB);
    float* outp = (float*)d_out;

    const int NB = cdiv(NN, 1024);
    // CSR build
    k_init_cnt<<<cdiv(NN, 256), 256>>>();
    k_count<<<cdiv(NE, 256), 256>>>(dst);
    k_scan1<<<NB, 1024>>>();
    k_scan2<<<1, 128>>>(NB);
    k_scan3<<<NB, 1024>>>();
    k_self<<<cdiv(NN, 256), 256>>>();
    k_edges<<<cdiv(NE, 256), 256>>>(src, dst);

    const int TPB = 256;
    int blocks32 = cdiv(NN * 32, TPB);
    int blocks16 = cdiv(cdiv(NN, 2) * 32, TPB);
    int blocks8  = cdiv(cdiv(NN, 4) * 32, TPB);
    int blocks4  = cdiv(cdiv(NN, 8) * 32, TPB);

    // encoder
    k_eg1<<<blocks4, TPB>>>(x, W[0], B[0], bufB);                       // fused agg+eg1
    gemm_t<0, false>(bufB, W[1], nullptr, bufA, 160, 80);               // eg2 matmul
    k_aggv<80, 32, 1, true><<<blocks32, TPB>>>(bufA, B[1], bufB);       // eg2 agg+b+relu
    gemm_t<0, false>(bufB, W[2], nullptr, bufA, 80, 40);                // eg3 matmul
    k_aggv<40, 16, 1, true><<<blocks16, TPB>>>(bufA, B[2], bufB);       // eg3 agg+b+relu
    gemm_s(bufB, W[3], nullptr, bufA, 40, 20, 0, 0);                    // eg4 matmul
    k_aggv<20, 8, 1, true><<<blocks8, TPB>>>(bufA, B[3], bufB);         // eg4 agg+b+relu
    // latent dense chain
    k_chain<<<cdiv(NN, 256), 256>>>(bufB, bufA, W[4], B[4], W[5], B[5], W[6], B[6], W[7], B[7]);
    // decoder
    k_aggv<20, 8, 0, false><<<blocks8, TPB>>>(bufA, nullptr, bufB);     // dg1 agg
    gemm_s(bufB, W[8], B[8], bufA, 20, 40, 1, 1);                       // dg1
    k_aggv<40, 16, 0, false><<<blocks16, TPB>>>(bufA, nullptr, bufB);   // dg2 agg
    gemm_t<1, true>(bufB, W[9], B[9], bufA, 40, 80);                    // dg2
    k_aggv<80, 32, 0, false><<<blocks32, TPB>>>(bufA, nullptr, bufB);   // dg3 agg
    gemm_t<1, true>(bufB, W[10], B[10], bufA, 80, 160);                 // dg3
    gemm_s(bufA, W[11], nullptr, bufB, 160, 3, 0, 0);                   // dg4 matmul
    k_agg3<2, true><<<blocks4, TPB>>>(bufB, B[11], outp);               // dg4 agg+b+tanh
}

// round 4
// speedup vs baseline: 1.3014x; 1.0107x over previous
#include <cuda_runtime.h>
#include <cuda_fp16.h>
#include <cuda_bf16.h>
#include <cstdint>

#define NN 100000
#define NE 1600000
#define NTOT (NE + NN)

// ---------------- scratch (device globals: allocation-free) ----------------
__device__ float  g_bufA[NN * 160];
__device__ float  g_bufB[NN * 160];
__device__ __half g_bufH[NN * 80];
__device__ int    g_cnt[NN];
__device__ float  g_dis[NN];
__device__ int    g_rowptr[NN + 1];
__device__ int    g_fill[NN];
__device__ int2   g_entries[NTOT];   // {src_node, float_bits(norm)} sorted by dst
__device__ int    g_bsums[128];

static inline int cdiv(int a, int b) { return (a + b - 1) / b; }

// ---------------- CSR build ----------------
__global__ void k_init_cnt() {
    int i = blockIdx.x * blockDim.x + threadIdx.x;
    if (i < NN) g_cnt[i] = 1;   // self-loop
}
__global__ void k_count(const int* __restrict__ dst) {
    int e = blockIdx.x * blockDim.x + threadIdx.x;
    if (e < NE) atomicAdd(&g_cnt[dst[e]], 1);
}
__global__ void k_scan1() {   // also computes g_dis
    __shared__ int s[1024];
    int i = blockIdx.x * 1024 + threadIdx.x;
    int v = (i < NN) ? g_cnt[i] : 0;
    if (i < NN) g_dis[i] = rsqrtf((float)v);
    s[threadIdx.x] = v;
    __syncthreads();
    for (int d = 1; d < 1024; d <<= 1) {
        int t = (threadIdx.x >= d) ? s[threadIdx.x - d] : 0;
        __syncthreads();
        s[threadIdx.x] += t;
        __syncthreads();
    }
    if (i < NN) g_rowptr[i + 1] = s[threadIdx.x];
    if (threadIdx.x == 1023) g_bsums[blockIdx.x] = s[1023];
}
__global__ void k_scan2(int nb) {
    __shared__ int s[128];
    int v = (threadIdx.x < nb) ? g_bsums[threadIdx.x] : 0;
    s[threadIdx.x] = v;
    __syncthreads();
    for (int d = 1; d < 128; d <<= 1) {
        int t = (threadIdx.x >= d) ? s[threadIdx.x - d] : 0;
        __syncthreads();
        s[threadIdx.x] += t;
        __syncthreads();
    }
    if (threadIdx.x < nb) g_bsums[threadIdx.x] = s[threadIdx.x] - v;
}
__global__ void k_scan3() {
    int i = blockIdx.x * 1024 + threadIdx.x;
    if (i < NN) g_rowptr[i + 1] += g_bsums[blockIdx.x];
    if (i == 0) g_rowptr[0] = 0;
}
__global__ void k_self() {
    int i = blockIdx.x * blockDim.x + threadIdx.x;
    if (i < NN) {
        int p = g_rowptr[i];
        float d = g_dis[i];
        g_entries[p] = make_int2(i, __float_as_int(d * d));
        g_fill[i] = p + 1;
    }
}
__global__ void k_edges(const int* __restrict__ src, const int* __restrict__ dst) {
    int e = blockIdx.x * blockDim.x + threadIdx.x;
    if (e < NE) {
        int s = src[e], d = dst[e];
        int p = atomicAdd(&g_fill[d], 1);
        g_entries[p] = make_int2(s, __float_as_int(g_dis[s] * g_dis[d]));
    }
}

// ---------------- scalar aggregation (C=3), unroll-4 ----------------
template <int ACT, bool BIAS>
__global__ void k_agg3(const float* __restrict__ in, const float* __restrict__ bias,
                       float* __restrict__ out) {
    int gwarp = (blockIdx.x * blockDim.x + threadIdx.x) >> 5;
    int lane = threadIdx.x & 31;
    int node = gwarp * 8 + lane / 4;
    int cl = lane & 3;
    if (node >= NN) return;
    int p0 = g_rowptr[node], p1 = g_rowptr[node + 1];
    float acc = 0.f;
    bool act3 = (cl < 3);
    int p = p0;
    for (; p + 4 <= p1; p += 4) {
        int2 e0 = __ldg(&g_entries[p]);
        int2 e1 = __ldg(&g_entries[p + 1]);
        int2 e2 = __ldg(&g_entries[p + 2]);
        int2 e3 = __ldg(&g_entries[p + 3]);
        if (act3) {
            float v0 = __ldg(in + (long)e0.x * 3 + cl);
            float v1 = __ldg(in + (long)e1.x * 3 + cl);
            float v2 = __ldg(in + (long)e2.x * 3 + cl);
            float v3 = __ldg(in + (long)e3.x * 3 + cl);
            acc = fmaf(__int_as_float(e0.y), v0, acc);
            acc = fmaf(__int_as_float(e1.y), v1, acc);
            acc = fmaf(__int_as_float(e2.y), v2, acc);
            acc = fmaf(__int_as_float(e3.y), v3, acc);
        }
    }
    for (; p < p1; p++) {
        int2 e = __ldg(&g_entries[p]);
        if (act3) {
            float v = __ldg(in + (long)e.x * 3 + cl);
            acc = fmaf(__int_as_float(e.y), v, acc);
        }
    }
    if (act3) {
        float v = acc;
        if (BIAS) v += bias[cl];
        if (ACT == 1) v = fmaxf(v, 0.f);
        if (ACT == 2) v = tanhf(v);
        out[(long)node * 3 + cl] = v;
    }
}

// ---------------- fp32 vectorized aggregation (C % 4 == 0), unroll-4 ----------------
template <int C, int SUB, int ACT, bool BIAS>
__global__ void k_aggv(const float* __restrict__ in, const float* __restrict__ bias,
                       float* __restrict__ out) {
    constexpr int NV = C / 4;
    static_assert(NV <= SUB, "SUB too small");
    const int nodesPerWarp = 32 / SUB;
    int gwarp = (blockIdx.x * blockDim.x + threadIdx.x) >> 5;
    int lane = threadIdx.x & 31;
    int node = gwarp * nodesPerWarp + lane / SUB;
    int vl = lane % SUB;
    if (node >= NN) return;
    int p0 = g_rowptr[node], p1 = g_rowptr[node + 1];
    float4 acc = make_float4(0.f, 0.f, 0.f, 0.f);
    bool active = (vl < NV);
    int p = p0;
    for (; p + 4 <= p1; p += 4) {
        int2 e0 = __ldg(&g_entries[p]);
        int2 e1 = __ldg(&g_entries[p + 1]);
        int2 e2 = __ldg(&g_entries[p + 2]);
        int2 e3 = __ldg(&g_entries[p + 3]);
        if (active) {
            float4 v0 = __ldg((const float4*)(in + (long)e0.x * C) + vl);
            float4 v1 = __ldg((const float4*)(in + (long)e1.x * C) + vl);
            float4 v2 = __ldg((const float4*)(in + (long)e2.x * C) + vl);
            float4 v3 = __ldg((const float4*)(in + (long)e3.x * C) + vl);
            float w0 = __int_as_float(e0.y), w1 = __int_as_float(e1.y);
            float w2 = __int_as_float(e2.y), w3 = __int_as_float(e3.y);
            acc.x = fmaf(w0, v0.x, acc.x); acc.y = fmaf(w0, v0.y, acc.y);
            acc.z = fmaf(w0, v0.z, acc.z); acc.w = fmaf(w0, v0.w, acc.w);
            acc.x = fmaf(w1, v1.x, acc.x); acc.y = fmaf(w1, v1.y, acc.y);
            acc.z = fmaf(w1, v1.z, acc.z); acc.w = fmaf(w1, v1.w, acc.w);
            acc.x = fmaf(w2, v2.x, acc.x); acc.y = fmaf(w2, v2.y, acc.y);
            acc.z = fmaf(w2, v2.z, acc.z); acc.w = fmaf(w2, v2.w, acc.w);
            acc.x = fmaf(w3, v3.x, acc.x); acc.y = fmaf(w3, v3.y, acc.y);
            acc.z = fmaf(w3, v3.z, acc.z); acc.w = fmaf(w3, v3.w, acc.w);
        }
    }
    for (; p < p1; p++) {
        int2 e = __ldg(&g_entries[p]);
        if (active) {
            float w = __int_as_float(e.y);
            float4 v = __ldg((const float4*)(in + (long)e.x * C) + vl);
            acc.x = fmaf(w, v.x, acc.x); acc.y = fmaf(w, v.y, acc.y);
            acc.z = fmaf(w, v.z, acc.z); acc.w = fmaf(w, v.w, acc.w);
        }
    }
    if (active) {
        if (BIAS) {
            float4 bv = __ldg((const float4*)bias + vl);
            acc.x += bv.x; acc.y += bv.y; acc.z += bv.z; acc.w += bv.w;
        }
        if (ACT == 1) {
            acc.x = fmaxf(acc.x, 0.f); acc.y = fmaxf(acc.y, 0.f);
            acc.z = fmaxf(acc.z, 0.f); acc.w = fmaxf(acc.w, 0.f);
        }
        *((float4*)(out + (long)node * C) + vl) = acc;
    }
}

// ---------------- fp16-input aggregation (C % 8 == 0), int4 loads, unroll-4 ----------------
__device__ __forceinline__ void accum8h(float* acc, int4 h, float w) {
    const __half2* hp = (const __half2*)&h;
#pragma unroll
    for (int i = 0; i < 4; i++) {
        float2 f = __half22float2(hp[i]);
        acc[2 * i]     = fmaf(w, f.x, acc[2 * i]);
        acc[2 * i + 1] = fmaf(w, f.y, acc[2 * i + 1]);
    }
}

template <int C, int SUB, int ACT, bool BIAS>
__global__ void k_aggvh(const __half* __restrict__ in, const float* __restrict__ bias,
                        float* __restrict__ out) {
    constexpr int NV = C / 8;     // int4 = 8 halves per lane
    static_assert(NV <= SUB, "SUB too small");
    const int nodesPerWarp = 32 / SUB;
    int gwarp = (blockIdx.x * blockDim.x + threadIdx.x) >> 5;
    int lane = threadIdx.x & 31;
    int node = gwarp * nodesPerWarp + lane / SUB;
    int vl = lane % SUB;
    if (node >= NN) return;
    int p0 = g_rowptr[node], p1 = g_rowptr[node + 1];
    float acc[8] = {};
    bool active = (vl < NV);
    int p = p0;
    for (; p + 4 <= p1; p += 4) {
        int2 e0 = __ldg(&g_entries[p]);
        int2 e1 = __ldg(&g_entries[p + 1]);
        int2 e2 = __ldg(&g_entries[p + 2]);
        int2 e3 = __ldg(&g_entries[p + 3]);
        if (active) {
            int4 h0 = __ldg((const int4*)(in + (long)e0.x * C) + vl);
            int4 h1 = __ldg((const int4*)(in + (long)e1.x * C) + vl);
            int4 h2 = __ldg((const int4*)(in + (long)e2.x * C) + vl);
            int4 h3 = __ldg((const int4*)(in + (long)e3.x * C) + vl);
            accum8h(acc, h0, __int_as_float(e0.y));
            accum8h(acc, h1, __int_as_float(e1.y));
            accum8h(acc, h2, __int_as_float(e2.y));
            accum8h(acc, h3, __int_as_float(e3.y));
        }
    }
    for (; p < p1; p++) {
        int2 e = __ldg(&g_entries[p]);
        if (active) {
            int4 h = __ldg((const int4*)(in + (long)e.x * C) + vl);
            accum8h(acc, h, __int_as_float(e.y));
        }
    }
    if (active) {
        if (BIAS) {
            const float4* bp = (const float4*)bias + vl * 2;
            float4 b0 = __ldg(bp), b1 = __ldg(bp + 1);
            acc[0] += b0.x; acc[1] += b0.y; acc[2] += b0.z; acc[3] += b0.w;
            acc[4] += b1.x; acc[5] += b1.y; acc[6] += b1.z; acc[7] += b1.w;
        }
        if (ACT == 1) {
#pragma unroll
            for (int i = 0; i < 8; i++) acc[i] = fmaxf(acc[i], 0.f);
        }
        float4* op = (float4*)(out + (long)node * C) + vl * 2;
        op[0] = make_float4(acc[0], acc[1], acc[2], acc[3]);
        op[1] = make_float4(acc[4], acc[5], acc[6], acc[7]);
    }
}

// ---------------- fused eg1: out = relu(agg(x, C=3) @ W(3x160) + b) ----------------
__global__ void __launch_bounds__(256)
k_eg1(const float* __restrict__ x, const float* __restrict__ W,
      const float* __restrict__ Bb, float* __restrict__ out) {
    __shared__ float sW[480];
    __shared__ float sB[160];
    for (int i = threadIdx.x; i < 480; i += 256) sW[i] = W[i];
    for (int i = threadIdx.x; i < 160; i += 256) sB[i] = Bb[i];
    __syncthreads();
    int gwarp = (blockIdx.x * blockDim.x + threadIdx.x) >> 5;
    int lane = threadIdx.x & 31;
    int nodeBase = gwarp * 8;
    int node = nodeBase + lane / 4;
    int cl = lane & 3;
    float acc = 0.f;
    if (node < NN) {
        int p0 = g_rowptr[node], p1 = g_rowptr[node + 1];
        bool act3 = (cl < 3);
        int p = p0;
        for (; p + 4 <= p1; p += 4) {
            int2 e0 = __ldg(&g_entries[p]);
            int2 e1 = __ldg(&g_entries[p + 1]);
            int2 e2 = __ldg(&g_entries[p + 2]);
            int2 e3 = __ldg(&g_entries[p + 3]);
            if (act3) {
                float v0 = __ldg(x + (long)e0.x * 3 + cl);
                float v1 = __ldg(x + (long)e1.x * 3 + cl);
                float v2 = __ldg(x + (long)e2.x * 3 + cl);
                float v3 = __ldg(x + (long)e3.x * 3 + cl);
                acc = fmaf(__int_as_float(e0.y), v0, acc);
                acc = fmaf(__int_as_float(e1.y), v1, acc);
                acc = fmaf(__int_as_float(e2.y), v2, acc);
                acc = fmaf(__int_as_float(e3.y), v3, acc);
            }
        }
        for (; p < p1; p++) {
            int2 e = __ldg(&g_entries[p]);
            if (act3) {
                float v = __ldg(x + (long)e.x * 3 + cl);
                acc = fmaf(__int_as_float(e.y), v, acc);
            }
        }
    }
#pragma unroll
    for (int j = 0; j < 8; j++) {
        int n2 = nodeBase + j;
        float a0 = __shfl_sync(0xffffffffu, acc, j * 4 + 0);
        float a1 = __shfl_sync(0xffffffffu, acc, j * 4 + 1);
        float a2 = __shfl_sync(0xffffffffu, acc, j * 4 + 2);
        if (n2 >= NN) break;
        float* op = out + (long)n2 * 160;
#pragma unroll
        for (int c0 = 0; c0 < 160; c0 += 32) {
            int c = c0 + lane;
            float v = sB[c];
            v = fmaf(a0, sW[c], v);
            v = fmaf(a1, sW[160 + c], v);
            v = fmaf(a2, sW[320 + c], v);
            op[c] = fmaxf(v, 0.f);
        }
    }
}

// ---------------- SIMT GEMM ----------------
#define BMS 64
#define BNS 64
#define BKS 16
#define TMS 4
#define TNS 4
template <bool OUTH>
__global__ void __launch_bounds__(256)
k_gemm(const float* __restrict__ A, const float* __restrict__ W,
       const float* __restrict__ bias, void* __restrict__ outv,
       int M, int K, int Nc, int act, int useBias) {
    __shared__ float sA[BKS][BMS + 1];
    __shared__ float sW[BKS][BNS];
    int tx = threadIdx.x % 16, ty = threadIdx.x / 16;
    int row0 = blockIdx.y * BMS, col0 = blockIdx.x * BNS;
    float acc[TMS][TNS] = {};
    for (int k0 = 0; k0 < K; k0 += BKS) {
        for (int i = threadIdx.x; i < BMS * BKS; i += 256) {
            int kk = i % BKS, m = i / BKS;
            int gm = row0 + m, gk = k0 + kk;
            sA[kk][m] = (gm < M && gk < K) ? A[(long)gm * K + gk] : 0.f;
        }
        for (int i = threadIdx.x; i < BKS * BNS; i += 256) {
            int n = i % BNS, kk = i / BNS;
            int gk = k0 + kk, gn = col0 + n;
            sW[kk][n] = (gk < K && gn < Nc) ? W[gk * Nc + gn] : 0.f;
        }
        __syncthreads();
#pragma unroll
        for (int kk = 0; kk < BKS; kk++) {
            float a[TMS];
#pragma unroll
            for (int i = 0; i < TMS; i++) a[i] = sA[kk][ty * TMS + i];
            float4 w4 = *(const float4*)&sW[kk][tx * TNS];
            float w[TNS] = {w4.x, w4.y, w4.z, w4.w};
#pragma unroll
            for (int i = 0; i < TMS; i++)
#pragma unroll
                for (int j = 0; j < TNS; j++) acc[i][j] = fmaf(a[i], w[j], acc[i][j]);
        }
        __syncthreads();
    }
#pragma unroll
    for (int i = 0; i < TMS; i++) {
        int gm = row0 + ty * TMS + i;
        if (gm >= M) continue;
#pragma unroll
        for (int j = 0; j < TNS; j++) {
            int gn = col0 + tx * TNS + j;
            if (gn >= Nc) continue;
            float v = acc[i][j];
            if (useBias) v += bias[gn];
            if (act == 1) v = fmaxf(v, 0.f);
            else if (act == 2) v = tanhf(v);
            if (OUTH) ((__half*)outv)[(long)gm * Nc + gn] = __float2half_rn(v);
            else ((float*)outv)[(long)gm * Nc + gn] = v;
        }
    }
}

// ---------------- 3xTF32 tensor-core GEMM ----------------
__device__ __forceinline__ uint32_t f2tf32(float x) {
    uint32_t r;
    asm("cvt.rna.tf32.f32 %0, %1;" : "=r"(r) : "f"(x));
    return r;
}
__device__ __forceinline__ void mma_tf32(float* c, uint32_t a0, uint32_t a1,
                                         uint32_t a2, uint32_t a3,
                                         uint32_t b0, uint32_t b1) {
    asm volatile(
        "mma.sync.aligned.m16n8k8.row.col.f32.tf32.tf32.f32 "
        "{%0,%1,%2,%3}, {%4,%5,%6,%7}, {%8,%9}, {%0,%1,%2,%3};\n"
        : "+f"(c[0]), "+f"(c[1]), "+f"(c[2]), "+f"(c[3])
        : "r"(a0), "r"(a1), "r"(a2), "r"(a3), "r"(b0), "r"(b1));
}

#define TBM 128
#define TBN 80
#define TBK 16
#define SA_STR 20
#define SB_STR 88

template <int ACT, bool BIAS, bool OUTH>
__global__ void __launch_bounds__(256)
k_gemm_tf32(const float* __restrict__ A, const float* __restrict__ W,
            const float* __restrict__ bias, void* __restrict__ outv,
            int M, int K, int Nc) {
    __shared__ uint32_t sAh[TBM * SA_STR];
    __shared__ uint32_t sAl[TBM * SA_STR];
    __shared__ uint32_t sBh[TBK * SB_STR];
    __shared__ uint32_t sBl[TBK * SB_STR];

    int tid = threadIdx.x;
    int wid = tid >> 5;
    int lane = tid & 31;
    int g = lane >> 2;
    int t = lane & 3;
    int wm = wid & 3;
    int wn = wid >> 2;
    int row0 = blockIdx.y * TBM;
    int col0 = blockIdx.x * TBN;

    float acc[2][5][4];
#pragma unroll
    for (int i = 0; i < 2; i++)
#pragma unroll
        for (int j = 0; j < 5; j++)
#pragma unroll
            for (int q = 0; q < 4; q++) acc[i][j][q] = 0.f;

    for (int k0 = 0; k0 < K; k0 += TBK) {
#pragma unroll
        for (int it = 0; it < 8; it++) {
            int idx = tid + it * 256;
            int m = idx >> 4, kk = idx & 15;
            int gm = row0 + m, gk = k0 + kk;
            float v = (gm < M && gk < K) ? A[(long)gm * K + gk] : 0.f;
            uint32_t hi = f2tf32(v);
            float rest = v - __uint_as_float(hi);
            sAh[m * SA_STR + kk] = hi;
            sAl[m * SA_STR + kk] = f2tf32(rest);
        }
#pragma unroll
        for (int it = 0; it < 5; it++) {
            int idx = tid + it * 256;
            int kk = idx / 80, n = idx - kk * 80;
            int gk = k0 + kk, gn = col0 + n;
            float v = (gk < K && gn < Nc) ? W[(long)gk * Nc + gn] : 0.f;
            uint32_t hi = f2tf32(v);
            float rest = v - __uint_as_float(hi);
            sBh[kk * SB_STR + n] = hi;
            sBl[kk * SB_STR + n] = f2tf32(rest);
        }
        __syncthreads();

#pragma unroll
        for (int ks = 0; ks < TBK; ks += 8) {
            uint32_t ah[2][4], al[2][4];
#pragma unroll
            for (int i = 0; i < 2; i++) {
                int r0 = wm * 32 + i * 16 + g;
                ah[i][0] = sAh[r0 * SA_STR + ks + t];
                ah[i][1] = sAh[(r0 + 8) * SA_STR + ks + t];
                ah[i][2] = sAh[r0 * SA_STR + ks + t + 4];
                ah[i][3] = sAh[(r0 + 8) * SA_STR + ks + t + 4];
                al[i][0] = sAl[r0 * SA_STR + ks + t];
                al[i][1] = sAl[(r0 + 8) * SA_STR + ks + t];
                al[i][2] = sAl[r0 * SA_STR + ks + t + 4];
                al[i][3] = sAl[(r0 + 8) * SA_STR + ks + t + 4];
            }
#pragma unroll
            for (int j = 0; j < 5; j++) {
                int c = wn * 40 + j * 8 + g;
                uint32_t bh0 = sBh[(ks + t) * SB_STR + c];
                uint32_t bh1 = sBh[(ks + t + 4) * SB_STR + c];
                uint32_t bl0 = sBl[(ks + t) * SB_STR + c];
                uint32_t bl1 = sBl[(ks + t + 4) * SB_STR + c];
#pragma unroll
                for (int i = 0; i < 2; i++) {
                    mma_tf32(acc[i][j], ah[i][0], ah[i][1], ah[i][2], ah[i][3], bh0, bh1);
                    mma_tf32(acc[i][j], ah[i][0], ah[i][1], ah[i][2], ah[i][3], bl0, bl1);
                    mma_tf32(acc[i][j], al[i][0], al[i][1], al[i][2], al[i][3], bh0, bh1);
                }
            }
        }
        __syncthreads();
    }

#pragma unroll
    for (int i = 0; i < 2; i++) {
        int rbase = row0 + wm * 32 + i * 16 + g;
#pragma unroll
        for (int j = 0; j < 5; j++) {
            int cbase = col0 + wn * 40 + j * 8 + t * 2;
#pragma unroll
            for (int q = 0; q < 4; q++) {
                int gm = rbase + ((q >= 2) ? 8 : 0);
                int gn = cbase + (q & 1);
                if (gm < M && gn < Nc) {
                    float v = acc[i][j][q];
                    if (BIAS) v += bias[gn];
                    if (ACT == 1) v = fmaxf(v, 0.f);
                    if (OUTH) ((__half*)outv)[(long)gm * Nc + gn] = __float2half_rn(v);
                    else ((float*)outv)[(long)gm * Nc + gn] = v;
                }
            }
        }
    }
}

// ---------------- fused dense chain ----------------
__global__ void __launch_bounds__(256)
k_chain(const float* __restrict__ in, float* __restrict__ out,
        const float* __restrict__ w1, const float* __restrict__ b1,
        const float* __restrict__ w2, const float* __restrict__ b2,
        const float* __restrict__ w3, const float* __restrict__ b3,
        const float* __restrict__ w4, const float* __restrict__ b4) {
    __shared__ float sw1[200], sb1[10], sw2[30], sb2[3], sw3[30], sb3[10], sw4[200], sb4[20];
    int tid = threadIdx.x;
    for (int i = tid; i < 200; i += 256) sw1[i] = w1[i];
    for (int i = tid; i < 10; i += 256) sb1[i] = b1[i];
    for (int i = tid; i < 30; i += 256) sw2[i] = w2[i];
    for (int i = tid; i < 3; i += 256) sb2[i] = b2[i];
    for (int i = tid; i < 30; i += 256) sw3[i] = w3[i];
    for (int i = tid; i < 10; i += 256) sb3[i] = b3[i];
    for (int i = tid; i < 200; i += 256) sw4[i] = w4[i];
    for (int i = tid; i < 20; i += 256) sb4[i] = b4[i];
    __syncthreads();

    int n = blockIdx.x * blockDim.x + tid;
    if (n >= NN) return;
    float h0[20];
    const float4* ip = (const float4*)(in + (long)n * 20);
#pragma unroll
    for (int i = 0; i < 5; i++) {
        float4 v = __ldg(ip + i);
        h0[i * 4 + 0] = v.x; h0[i * 4 + 1] = v.y; h0[i * 4 + 2] = v.z; h0[i * 4 + 3] = v.w;
    }
    float h1[10];
#pragma unroll
    for (int j = 0; j < 10; j++) {
        float s = sb1[j];
#pragma unroll
        for (int i = 0; i < 20; i++) s = fmaf(h0[i], sw1[i * 10 + j], s);
        h1[j] = fmaxf(s, 0.f);
    }
    float z[3];
#pragma unroll
    for (int j = 0; j < 3; j++) {
        float s = sb2[j];
#pragma unroll
        for (int i = 0; i < 10; i++) s = fmaf(h1[i], sw2[i * 3 + j], s);
        z[j] = s;
    }
    float h2[10];
#pragma unroll
    for (int j = 0; j < 10; j++) {
        float s = sb3[j];
#pragma unroll
        for (int i = 0; i < 3; i++) s = fmaf(z[i], sw3[i * 10 + j], s);
        h2[j] = fmaxf(s, 0.f);
    }
    float* op = out + (long)n * 20;
#pragma unroll
    for (int j = 0; j < 20; j++) {
        float s = sb4[j];
#pragma unroll
        for (int i = 0; i < 10; i++) s = fmaf(h2[i], sw4[i * 20 + j], s);
        op[j] = fmaxf(s, 0.f);
    }
}

// ---------------- driver ----------------
template <bool OUTH>
static void gemm_s(const float* A, const float* W, const float* b, void* o,
                   int K, int Nc, int act, int useBias) {
    dim3 g(cdiv(Nc, BNS), cdiv(NN, BMS));
    k_gemm<OUTH><<<g, 256>>>(A, W, b, o, NN, K, Nc, act, useBias);
}
template <int ACT, bool BIAS, bool OUTH>
static void gemm_t(const float* A, const float* W, const float* b, void* o, int K, int Nc) {
    dim3 g(cdiv(Nc, TBN), cdiv(NN, TBM));
    k_gemm_tf32<ACT, BIAS, OUTH><<<g, 256>>>(A, W, b, o, NN, K, Nc);
}

extern "C" void kernel_launch(void* const* d_in, const int* in_sizes, int n_in,
                              void* d_out, int out_size) {
    const float* x = (const float*)d_in[0];
    const int* ei = (const int*)d_in[1];
    const int* src = ei;
    const int* dst = ei + NE;
    const float* W[12];
    const float* B[12];
    for (int i = 0; i < 12; i++) {
        W[i] = (const float*)d_in[2 + 2 * i];
        B[i] = (const float*)d_in[3 + 2 * i];
    }
    float* bufA; cudaGetSymbolAddress((void**)&bufA, g_bufA);
    float* bufB; cudaGetSymbolAddress((void**)&bufB, g_bufB);
    __half* bufH; cudaGetSymbolAddress((void**)&bufH, g_bufH);
    float* outp = (float*)d_out;

    const int NB = cdiv(NN, 1024);
    // CSR build
    k_init_cnt<<<cdiv(NN, 256), 256>>>();
    k_count<<<cdiv(NE, 256), 256>>>(dst);
    k_scan1<<<NB, 1024>>>();
    k_scan2<<<1, 128>>>(NB);
    k_scan3<<<NB, 1024>>>();
    k_self<<<cdiv(NN, 256), 256>>>();
    k_edges<<<cdiv(NE, 256), 256>>>(src, dst);

    const int TPB = 256;
    int blocks16 = cdiv(cdiv(NN, 2) * 32, TPB);   // SUB=16
    int blocks8  = cdiv(cdiv(NN, 4) * 32, TPB);   // SUB=8
    int blocks4  = cdiv(cdiv(NN, 8) * 32, TPB);   // SUB=4 scalar C=3

    // encoder
    k_eg1<<<blocks4, TPB>>>(x, W[0], B[0], bufB);                        // fused agg+eg1
    gemm_t<0, false, true>(bufB, W[1], nullptr, bufH, 160, 80);          // eg2 matmul -> fp16
    k_aggvh<80, 16, 1, true><<<blocks16, TPB>>>(bufH, B[1], bufA);       // eg2 agg+b+relu
    gemm_t<0, false, true>(bufA, W[2], nullptr, bufH, 80, 40);           // eg3 matmul -> fp16
    k_aggvh<40, 8, 1, true><<<blocks8, TPB>>>(bufH, B[2], bufB);         // eg3 agg+b+relu
    gemm_s<false>(bufB, W[3], nullptr, bufA, 40, 20, 0, 0);              // eg4 matmul
    k_aggv<20, 8, 1, true><<<blocks8, TPB>>>(bufA, B[3], bufB);          // eg4 agg+b+relu
    // latent dense chain
    k_chain<<<cdiv(NN, 256), 256>>>(bufB, bufA, W[4], B[4], W[5], B[5], W[6], B[6], W[7], B[7]);
    // decoder
    k_aggv<20, 8, 0, false><<<blocks8, TPB>>>(bufA, nullptr, bufB);      // dg1 agg
    gemm_s<true>(bufB, W[8], B[8], bufH, 20, 40, 1, 1);                  // dg1 relu -> fp16
    k_aggvh<40, 8, 0, false><<<blocks8, TPB>>>(bufH, nullptr, bufA);     // dg2 agg
    gemm_t<1, true, true>(bufA, W[9], B[9], bufH, 40, 80);               // dg2 relu -> fp16
    k_aggvh<80, 16, 0, false><<<blocks16, TPB>>>(bufH, nullptr, bufB);   // dg3 agg
    gemm_t<1, true, false>(bufB, W[10], B[10], bufA, 80, 160);           // dg3 relu
    gemm_s<false>(bufA, W[11], nullptr, bufB, 160, 3, 0, 0);             // dg4 matmul
    k_agg3<2, true><<<blocks4, TPB>>>(bufB, B[11], outp);                // dg4 agg+b+tanh
}

// round 5
// speedup vs baseline: 1.3789x; 1.0595x over previous
#include <cuda_runtime.h>
#include <cuda_fp16.h>
#include <cuda_bf16.h>
#include <cstdint>

#define NN 100000
#define NE 1600000
#define NTOT (NE + NN)

// ---------------- scratch (device globals: allocation-free) ----------------
__device__ float  g_bufA[NN * 160];
__device__ float  g_bufB[NN * 160];
__device__ __half g_bufH[NN * 80];
__device__ int    g_cnt[NN];
__device__ float  g_dis[NN];
__device__ int    g_rowptr[NN + 1];
__device__ int    g_fill[NN];
__device__ int2   g_entries[NTOT];   // {src_node, float_bits(norm)} sorted by dst
__device__ int    g_bsums[128];

static inline int cdiv(int a, int b) { return (a + b - 1) / b; }

// ---------------- CSR build ----------------
__global__ void k_init_cnt() {
    int i = blockIdx.x * blockDim.x + threadIdx.x;
    if (i < NN) g_cnt[i] = 1;   // self-loop
}
__global__ void k_count(const int* __restrict__ dst) {
    int e = blockIdx.x * blockDim.x + threadIdx.x;
    if (e < NE) atomicAdd(&g_cnt[dst[e]], 1);
}
__global__ void k_scan1() {   // also computes g_dis
    __shared__ int s[1024];
    int i = blockIdx.x * 1024 + threadIdx.x;
    int v = (i < NN) ? g_cnt[i] : 0;
    if (i < NN) g_dis[i] = rsqrtf((float)v);
    s[threadIdx.x] = v;
    __syncthreads();
    for (int d = 1; d < 1024; d <<= 1) {
        int t = (threadIdx.x >= d) ? s[threadIdx.x - d] : 0;
        __syncthreads();
        s[threadIdx.x] += t;
        __syncthreads();
    }
    if (i < NN) g_rowptr[i + 1] = s[threadIdx.x];
    if (threadIdx.x == 1023) g_bsums[blockIdx.x] = s[1023];
}
__global__ void k_scan2(int nb) {
    __shared__ int s[128];
    int v = (threadIdx.x < nb) ? g_bsums[threadIdx.x] : 0;
    s[threadIdx.x] = v;
    __syncthreads();
    for (int d = 1; d < 128; d <<= 1) {
        int t = (threadIdx.x >= d) ? s[threadIdx.x - d] : 0;
        __syncthreads();
        s[threadIdx.x] += t;
        __syncthreads();
    }
    if (threadIdx.x < nb) g_bsums[threadIdx.x] = s[threadIdx.x] - v;
}
__global__ void k_scan3() {
    int i = blockIdx.x * 1024 + threadIdx.x;
    if (i < NN) g_rowptr[i + 1] += g_bsums[blockIdx.x];
    if (i == 0) g_rowptr[0] = 0;
}
__global__ void k_self() {
    int i = blockIdx.x * blockDim.x + threadIdx.x;
    if (i < NN) {
        int p = g_rowptr[i];
        float d = g_dis[i];
        g_entries[p] = make_int2(i, __float_as_int(d * d));
        g_fill[i] = p + 1;
    }
}
__global__ void k_edges(const int* __restrict__ src, const int* __restrict__ dst) {
    int e = blockIdx.x * blockDim.x + threadIdx.x;
    if (e < NE) {
        int s = src[e], d = dst[e];
        int p = atomicAdd(&g_fill[d], 1);
        g_entries[p] = make_int2(s, __float_as_int(g_dis[s] * g_dis[d]));
    }
}

// ---------------- scalar aggregation (C=3), unroll-4 ----------------
template <int ACT, bool BIAS>
__global__ void k_agg3(const float* __restrict__ in, const float* __restrict__ bias,
                       float* __restrict__ out) {
    int gwarp = (blockIdx.x * blockDim.x + threadIdx.x) >> 5;
    int lane = threadIdx.x & 31;
    int node = gwarp * 8 + lane / 4;
    int cl = lane & 3;
    if (node >= NN) return;
    int p0 = g_rowptr[node], p1 = g_rowptr[node + 1];
    float acc = 0.f;
    bool act3 = (cl < 3);
    int p = p0;
    for (; p + 4 <= p1; p += 4) {
        int2 e0 = __ldg(&g_entries[p]);
        int2 e1 = __ldg(&g_entries[p + 1]);
        int2 e2 = __ldg(&g_entries[p + 2]);
        int2 e3 = __ldg(&g_entries[p + 3]);
        if (act3) {
            float v0 = __ldg(in + (long)e0.x * 3 + cl);
            float v1 = __ldg(in + (long)e1.x * 3 + cl);
            float v2 = __ldg(in + (long)e2.x * 3 + cl);
            float v3 = __ldg(in + (long)e3.x * 3 + cl);
            acc = fmaf(__int_as_float(e0.y), v0, acc);
            acc = fmaf(__int_as_float(e1.y), v1, acc);
            acc = fmaf(__int_as_float(e2.y), v2, acc);
            acc = fmaf(__int_as_float(e3.y), v3, acc);
        }
    }
    for (; p < p1; p++) {
        int2 e = __ldg(&g_entries[p]);
        if (act3) {
            float v = __ldg(in + (long)e.x * 3 + cl);
            acc = fmaf(__int_as_float(e.y), v, acc);
        }
    }
    if (act3) {
        float v = acc;
        if (BIAS) v += bias[cl];
        if (ACT == 1) v = fmaxf(v, 0.f);
        if (ACT == 2) v = tanhf(v);
        out[(long)node * 3 + cl] = v;
    }
}

// ---------------- fp32 vectorized aggregation (C % 4 == 0), unroll-4 ----------------
template <int C, int SUB, int ACT, bool BIAS>
__global__ void k_aggv(const float* __restrict__ in, const float* __restrict__ bias,
                       float* __restrict__ out) {
    constexpr int NV = C / 4;
    static_assert(NV <= SUB, "SUB too small");
    const int nodesPerWarp = 32 / SUB;
    int gwarp = (blockIdx.x * blockDim.x + threadIdx.x) >> 5;
    int lane = threadIdx.x & 31;
    int node = gwarp * nodesPerWarp + lane / SUB;
    int vl = lane % SUB;
    if (node >= NN) return;
    int p0 = g_rowptr[node], p1 = g_rowptr[node + 1];
    float4 acc = make_float4(0.f, 0.f, 0.f, 0.f);
    bool active = (vl < NV);
    int p = p0;
    for (; p + 4 <= p1; p += 4) {
        int2 e0 = __ldg(&g_entries[p]);
        int2 e1 = __ldg(&g_entries[p + 1]);
        int2 e2 = __ldg(&g_entries[p + 2]);
        int2 e3 = __ldg(&g_entries[p + 3]);
        if (active) {
            float4 v0 = __ldg((const float4*)(in + (long)e0.x * C) + vl);
            float4 v1 = __ldg((const float4*)(in + (long)e1.x * C) + vl);
            float4 v2 = __ldg((const float4*)(in + (long)e2.x * C) + vl);
            float4 v3 = __ldg((const float4*)(in + (long)e3.x * C) + vl);
            float w0 = __int_as_float(e0.y), w1 = __int_as_float(e1.y);
            float w2 = __int_as_float(e2.y), w3 = __int_as_float(e3.y);
            acc.x = fmaf(w0, v0.x, acc.x); acc.y = fmaf(w0, v0.y, acc.y);
            acc.z = fmaf(w0, v0.z, acc.z); acc.w = fmaf(w0, v0.w, acc.w);
            acc.x = fmaf(w1, v1.x, acc.x); acc.y = fmaf(w1, v1.y, acc.y);
            acc.z = fmaf(w1, v1.z, acc.z); acc.w = fmaf(w1, v1.w, acc.w);
            acc.x = fmaf(w2, v2.x, acc.x); acc.y = fmaf(w2, v2.y, acc.y);
            acc.z = fmaf(w2, v2.z, acc.z); acc.w = fmaf(w2, v2.w, acc.w);
            acc.x = fmaf(w3, v3.x, acc.x); acc.y = fmaf(w3, v3.y, acc.y);
            acc.z = fmaf(w3, v3.z, acc.z); acc.w = fmaf(w3, v3.w, acc.w);
        }
    }
    for (; p < p1; p++) {
        int2 e = __ldg(&g_entries[p]);
        if (active) {
            float w = __int_as_float(e.y);
            float4 v = __ldg((const float4*)(in + (long)e.x * C) + vl);
            acc.x = fmaf(w, v.x, acc.x); acc.y = fmaf(w, v.y, acc.y);
            acc.z = fmaf(w, v.z, acc.z); acc.w = fmaf(w, v.w, acc.w);
        }
    }
    if (active) {
        if (BIAS) {
            float4 bv = __ldg((const float4*)bias + vl);
            acc.x += bv.x; acc.y += bv.y; acc.z += bv.z; acc.w += bv.w;
        }
        if (ACT == 1) {
            acc.x = fmaxf(acc.x, 0.f); acc.y = fmaxf(acc.y, 0.f);
            acc.z = fmaxf(acc.z, 0.f); acc.w = fmaxf(acc.w, 0.f);
        }
        *((float4*)(out + (long)node * C) + vl) = acc;
    }
}

// ---------------- fp16-input aggregation (C % 8 == 0), int4 loads, unroll-4 ----------------
__device__ __forceinline__ void accum8h(float* acc, int4 h, float w) {
    const __half2* hp = (const __half2*)&h;
#pragma unroll
    for (int i = 0; i < 4; i++) {
        float2 f = __half22float2(hp[i]);
        acc[2 * i]     = fmaf(w, f.x, acc[2 * i]);
        acc[2 * i + 1] = fmaf(w, f.y, acc[2 * i + 1]);
    }
}

template <int C, int SUB, int ACT, bool BIAS>
__global__ void k_aggvh(const __half* __restrict__ in, const float* __restrict__ bias,
                        float* __restrict__ out) {
    constexpr int NV = C / 8;
    static_assert(NV <= SUB, "SUB too small");
    const int nodesPerWarp = 32 / SUB;
    int gwarp = (blockIdx.x * blockDim.x + threadIdx.x) >> 5;
    int lane = threadIdx.x & 31;
    int node = gwarp * nodesPerWarp + lane / SUB;
    int vl = lane % SUB;
    if (node >= NN) return;
    int p0 = g_rowptr[node], p1 = g_rowptr[node + 1];
    float acc[8] = {};
    bool active = (vl < NV);
    int p = p0;
    for (; p + 4 <= p1; p += 4) {
        int2 e0 = __ldg(&g_entries[p]);
        int2 e1 = __ldg(&g_entries[p + 1]);
        int2 e2 = __ldg(&g_entries[p + 2]);
        int2 e3 = __ldg(&g_entries[p + 3]);
        if (active) {
            int4 h0 = __ldg((const int4*)(in + (long)e0.x * C) + vl);
            int4 h1 = __ldg((const int4*)(in + (long)e1.x * C) + vl);
            int4 h2 = __ldg((const int4*)(in + (long)e2.x * C) + vl);
            int4 h3 = __ldg((const int4*)(in + (long)e3.x * C) + vl);
            accum8h(acc, h0, __int_as_float(e0.y));
            accum8h(acc, h1, __int_as_float(e1.y));
            accum8h(acc, h2, __int_as_float(e2.y));
            accum8h(acc, h3, __int_as_float(e3.y));
        }
    }
    for (; p < p1; p++) {
        int2 e = __ldg(&g_entries[p]);
        if (active) {
            int4 h = __ldg((const int4*)(in + (long)e.x * C) + vl);
            accum8h(acc, h, __int_as_float(e.y));
        }
    }
    if (active) {
        if (BIAS) {
            const float4* bp = (const float4*)bias + vl * 2;
            float4 b0 = __ldg(bp), b1 = __ldg(bp + 1);
            acc[0] += b0.x; acc[1] += b0.y; acc[2] += b0.z; acc[3] += b0.w;
            acc[4] += b1.x; acc[5] += b1.y; acc[6] += b1.z; acc[7] += b1.w;
        }
        if (ACT == 1) {
#pragma unroll
            for (int i = 0; i < 8; i++) acc[i] = fmaxf(acc[i], 0.f);
        }
        float4* op = (float4*)(out + (long)node * C) + vl * 2;
        op[0] = make_float4(acc[0], acc[1], acc[2], acc[3]);
        op[1] = make_float4(acc[4], acc[5], acc[6], acc[7]);
    }
}

// ---------------- fused eg1: out = relu(agg(x, C=3) @ W(3x160) + b) ----------------
__global__ void __launch_bounds__(256)
k_eg1(const float* __restrict__ x, const float* __restrict__ W,
      const float* __restrict__ Bb, float* __restrict__ out) {
    __shared__ float sW[480];
    __shared__ float sB[160];
    for (int i = threadIdx.x; i < 480; i += 256) sW[i] = W[i];
    for (int i = threadIdx.x; i < 160; i += 256) sB[i] = Bb[i];
    __syncthreads();
    int gwarp = (blockIdx.x * blockDim.x + threadIdx.x) >> 5;
    int lane = threadIdx.x & 31;
    int nodeBase = gwarp * 8;
    int node = nodeBase + lane / 4;
    int cl = lane & 3;
    float acc = 0.f;
    if (node < NN) {
        int p0 = g_rowptr[node], p1 = g_rowptr[node + 1];
        bool act3 = (cl < 3);
        int p = p0;
        for (; p + 4 <= p1; p += 4) {
            int2 e0 = __ldg(&g_entries[p]);
            int2 e1 = __ldg(&g_entries[p + 1]);
            int2 e2 = __ldg(&g_entries[p + 2]);
            int2 e3 = __ldg(&g_entries[p + 3]);
            if (act3) {
                float v0 = __ldg(x + (long)e0.x * 3 + cl);
                float v1 = __ldg(x + (long)e1.x * 3 + cl);
                float v2 = __ldg(x + (long)e2.x * 3 + cl);
                float v3 = __ldg(x + (long)e3.x * 3 + cl);
                acc = fmaf(__int_as_float(e0.y), v0, acc);
                acc = fmaf(__int_as_float(e1.y), v1, acc);
                acc = fmaf(__int_as_float(e2.y), v2, acc);
                acc = fmaf(__int_as_float(e3.y), v3, acc);
            }
        }
        for (; p < p1; p++) {
            int2 e = __ldg(&g_entries[p]);
            if (act3) {
                float v = __ldg(x + (long)e.x * 3 + cl);
                acc = fmaf(__int_as_float(e.y), v, acc);
            }
        }
    }
#pragma unroll
    for (int j = 0; j < 8; j++) {
        int n2 = nodeBase + j;
        float a0 = __shfl_sync(0xffffffffu, acc, j * 4 + 0);
        float a1 = __shfl_sync(0xffffffffu, acc, j * 4 + 1);
        float a2 = __shfl_sync(0xffffffffu, acc, j * 4 + 2);
        if (n2 >= NN) break;
        float* op = out + (long)n2 * 160;
#pragma unroll
        for (int c0 = 0; c0 < 160; c0 += 32) {
            int c = c0 + lane;
            float v = sB[c];
            v = fmaf(a0, sW[c], v);
            v = fmaf(a1, sW[160 + c], v);
            v = fmaf(a2, sW[320 + c], v);
            op[c] = fmaxf(v, 0.f);
        }
    }
}

// ---------------- thread-per-node dense: out = act(in[n]@W + b) ----------------
// K % 4 == 0. Weights staged in smem. Work exactly proportional to K*NC.
template <int K, int NC, int ACT, bool BIAS, bool OUTH>
__global__ void __launch_bounds__(256)
k_dense(const float* __restrict__ in, const float* __restrict__ W,
        const float* __restrict__ bias, void* __restrict__ outv) {
    __shared__ float sW[K * NC];
    __shared__ float sB[NC];
    for (int i = threadIdx.x; i < K * NC; i += 256) sW[i] = W[i];
    if (BIAS) for (int i = threadIdx.x; i < NC; i += 256) sB[i] = bias[i];
    __syncthreads();
    int n = blockIdx.x * blockDim.x + threadIdx.x;
    if (n >= NN) return;
    float acc[NC];
#pragma unroll
    for (int c = 0; c < NC; c++) acc[c] = BIAS ? sB[c] : 0.f;
    const float4* ip = (const float4*)(in + (long)n * K);
#pragma unroll
    for (int k4 = 0; k4 < K / 4; k4++) {
        float4 v = __ldg(ip + k4);
#pragma unroll
        for (int c = 0; c < NC; c++) {
            acc[c] = fmaf(v.x, sW[(k4 * 4 + 0) * NC + c], acc[c]);
            acc[c] = fmaf(v.y, sW[(k4 * 4 + 1) * NC + c], acc[c]);
            acc[c] = fmaf(v.z, sW[(k4 * 4 + 2) * NC + c], acc[c]);
            acc[c] = fmaf(v.w, sW[(k4 * 4 + 3) * NC + c], acc[c]);
        }
    }
#pragma unroll
    for (int c = 0; c < NC; c++) {
        float v = acc[c];
        if (ACT == 1) v = fmaxf(v, 0.f);
        if (OUTH) ((__half*)outv)[(long)n * NC + c] = __float2half_rn(v);
        else ((float*)outv)[(long)n * NC + c] = v;
    }
}

// ---------------- 3xTF32 tensor-core GEMM ----------------
__device__ __forceinline__ uint32_t f2tf32(float x) {
    uint32_t r;
    asm("cvt.rna.tf32.f32 %0, %1;" : "=r"(r) : "f"(x));
    return r;
}
__device__ __forceinline__ void mma_tf32(float* c, uint32_t a0, uint32_t a1,
                                         uint32_t a2, uint32_t a3,
                                         uint32_t b0, uint32_t b1) {
    asm volatile(
        "mma.sync.aligned.m16n8k8.row.col.f32.tf32.tf32.f32 "
        "{%0,%1,%2,%3}, {%4,%5,%6,%7}, {%8,%9}, {%0,%1,%2,%3};\n"
        : "+f"(c[0]), "+f"(c[1]), "+f"(c[2]), "+f"(c[3])
        : "r"(a0), "r"(a1), "r"(a2), "r"(a3), "r"(b0), "r"(b1));
}

#define TBM 128
#define TBN 80
#define TBK 16
#define SA_STR 20
#define SB_STR 88

template <int ACT, bool BIAS, bool OUTH>
__global__ void __launch_bounds__(256)
k_gemm_tf32(const float* __restrict__ A, const float* __restrict__ W,
            const float* __restrict__ bias, void* __restrict__ outv,
            int M, int K, int Nc) {
    __shared__ uint32_t sAh[TBM * SA_STR];
    __shared__ uint32_t sAl[TBM * SA_STR];
    __shared__ uint32_t sBh[TBK * SB_STR];
    __shared__ uint32_t sBl[TBK * SB_STR];

    int tid = threadIdx.x;
    int wid = tid >> 5;
    int lane = tid & 31;
    int g = lane >> 2;
    int t = lane & 3;
    int wm = wid & 3;
    int wn = wid >> 2;
    int row0 = blockIdx.y * TBM;
    int col0 = blockIdx.x * TBN;

    float acc[2][5][4];
#pragma unroll
    for (int i = 0; i < 2; i++)
#pragma unroll
        for (int j = 0; j < 5; j++)
#pragma unroll
            for (int q = 0; q < 4; q++) acc[i][j][q] = 0.f;

    for (int k0 = 0; k0 < K; k0 += TBK) {
#pragma unroll
        for (int it = 0; it < 8; it++) {
            int idx = tid + it * 256;
            int m = idx >> 4, kk = idx & 15;
            int gm = row0 + m, gk = k0 + kk;
            float v = (gm < M && gk < K) ? A[(long)gm * K + gk] : 0.f;
            uint32_t hi = f2tf32(v);
            float rest = v - __uint_as_float(hi);
            sAh[m * SA_STR + kk] = hi;
            sAl[m * SA_STR + kk] = f2tf32(rest);
        }
#pragma unroll
        for (int it = 0; it < 5; it++) {
            int idx = tid + it * 256;
            int kk = idx / 80, n = idx - kk * 80;
            int gk = k0 + kk, gn = col0 + n;
            float v = (gk < K && gn < Nc) ? W[(long)gk * Nc + gn] : 0.f;
            uint32_t hi = f2tf32(v);
            float rest = v - __uint_as_float(hi);
            sBh[kk * SB_STR + n] = hi;
            sBl[kk * SB_STR + n] = f2tf32(rest);
        }
        __syncthreads();

#pragma unroll
        for (int ks = 0; ks < TBK; ks += 8) {
            uint32_t ah[2][4], al[2][4];
#pragma unroll
            for (int i = 0; i < 2; i++) {
                int r0 = wm * 32 + i * 16 + g;
                ah[i][0] = sAh[r0 * SA_STR + ks + t];
                ah[i][1] = sAh[(r0 + 8) * SA_STR + ks + t];
                ah[i][2] = sAh[r0 * SA_STR + ks + t + 4];
                ah[i][3] = sAh[(r0 + 8) * SA_STR + ks + t + 4];
                al[i][0] = sAl[r0 * SA_STR + ks + t];
                al[i][1] = sAl[(r0 + 8) * SA_STR + ks + t];
                al[i][2] = sAl[r0 * SA_STR + ks + t + 4];
                al[i][3] = sAl[(r0 + 8) * SA_STR + ks + t + 4];
            }
#pragma unroll
            for (int j = 0; j < 5; j++) {
                int c = wn * 40 + j * 8 + g;
                uint32_t bh0 = sBh[(ks + t) * SB_STR + c];
                uint32_t bh1 = sBh[(ks + t + 4) * SB_STR + c];
                uint32_t bl0 = sBl[(ks + t) * SB_STR + c];
                uint32_t bl1 = sBl[(ks + t + 4) * SB_STR + c];
#pragma unroll
                for (int i = 0; i < 2; i++) {
                    mma_tf32(acc[i][j], ah[i][0], ah[i][1], ah[i][2], ah[i][3], bh0, bh1);
                    mma_tf32(acc[i][j], ah[i][0], ah[i][1], ah[i][2], ah[i][3], bl0, bl1);
                    mma_tf32(acc[i][j], al[i][0], al[i][1], al[i][2], al[i][3], bh0, bh1);
                }
            }
        }
        __syncthreads();
    }

#pragma unroll
    for (int i = 0; i < 2; i++) {
        int rbase = row0 + wm * 32 + i * 16 + g;
#pragma unroll
        for (int j = 0; j < 5; j++) {
            int cbase = col0 + wn * 40 + j * 8 + t * 2;
#pragma unroll
            for (int q = 0; q < 4; q++) {
                int gm = rbase + ((q >= 2) ? 8 : 0);
                int gn = cbase + (q & 1);
                if (gm < M && gn < Nc) {
                    float v = acc[i][j][q];
                    if (BIAS) v += bias[gn];
                    if (ACT == 1) v = fmaxf(v, 0.f);
                    if (OUTH) ((__half*)outv)[(long)gm * Nc + gn] = __float2half_rn(v);
                    else ((float*)outv)[(long)gm * Nc + gn] = v;
                }
            }
        }
    }
}

// ---------------- fused dense chain ----------------
__global__ void __launch_bounds__(256)
k_chain(const float* __restrict__ in, float* __restrict__ out,
        const float* __restrict__ w1, const float* __restrict__ b1,
        const float* __restrict__ w2, const float* __restrict__ b2,
        const float* __restrict__ w3, const float* __restrict__ b3,
        const float* __restrict__ w4, const float* __restrict__ b4) {
    __shared__ float sw1[200], sb1[10], sw2[30], sb2[3], sw3[30], sb3[10], sw4[200], sb4[20];
    int tid = threadIdx.x;
    for (int i = tid; i < 200; i += 256) sw1[i] = w1[i];
    for (int i = tid; i < 10; i += 256) sb1[i] = b1[i];
    for (int i = tid; i < 30; i += 256) sw2[i] = w2[i];
    for (int i = tid; i < 3; i += 256) sb2[i] = b2[i];
    for (int i = tid; i < 30; i += 256) sw3[i] = w3[i];
    for (int i = tid; i < 10; i += 256) sb3[i] = b3[i];
    for (int i = tid; i < 200; i += 256) sw4[i] = w4[i];
    for (int i = tid; i < 20; i += 256) sb4[i] = b4[i];
    __syncthreads();

    int n = blockIdx.x * blockDim.x + tid;
    if (n >= NN) return;
    float h0[20];
    const float4* ip = (const float4*)(in + (long)n * 20);
#pragma unroll
    for (int i = 0; i < 5; i++) {
        float4 v = __ldg(ip + i);
        h0[i * 4 + 0] = v.x; h0[i * 4 + 1] = v.y; h0[i * 4 + 2] = v.z; h0[i * 4 + 3] = v.w;
    }
    float h1[10];
#pragma unroll
    for (int j = 0; j < 10; j++) {
        float s = sb1[j];
#pragma unroll
        for (int i = 0; i < 20; i++) s = fmaf(h0[i], sw1[i * 10 + j], s);
        h1[j] = fmaxf(s, 0.f);
    }
    float z[3];
#pragma unroll
    for (int j = 0; j < 3; j++) {
        float s = sb2[j];
#pragma unroll
        for (int i = 0; i < 10; i++) s = fmaf(h1[i], sw2[i * 3 + j], s);
        z[j] = s;
    }
    float h2[10];
#pragma unroll
    for (int j = 0; j < 10; j++) {
        float s = sb3[j];
#pragma unroll
        for (int i = 0; i < 3; i++) s = fmaf(z[i], sw3[i * 10 + j], s);
        h2[j] = fmaxf(s, 0.f);
    }
    float* op = out + (long)n * 20;
#pragma unroll
    for (int j = 0; j < 20; j++) {
        float s = sb4[j];
#pragma unroll
        for (int i = 0; i < 10; i++) s = fmaf(h2[i], sw4[i * 20 + j], s);
        op[j] = fmaxf(s, 0.f);
    }
}

// ---------------- driver ----------------
template <int ACT, bool BIAS, bool OUTH>
static void gemm_t(const float* A, const float* W, const float* b, void* o, int K, int Nc) {
    dim3 g(cdiv(Nc, TBN), cdiv(NN, TBM));
    k_gemm_tf32<ACT, BIAS, OUTH><<<g, 256>>>(A, W, b, o, NN, K, Nc);
}

extern "C" void kernel_launch(void* const* d_in, const int* in_sizes, int n_in,
                              void* d_out, int out_size) {
    const float* x = (const float*)d_in[0];
    const int* ei = (const int*)d_in[1];
    const int* src = ei;
    const int* dst = ei + NE;
    const float* W[12];
    const float* B[12];
    for (int i = 0; i < 12; i++) {
        W[i] = (const float*)d_in[2 + 2 * i];
        B[i] = (const float*)d_in[3 + 2 * i];
    }
    float* bufA; cudaGetSymbolAddress((void**)&bufA, g_bufA);
    float* bufB; cudaGetSymbolAddress((void**)&bufB, g_bufB);
    __half* bufH; cudaGetSymbolAddress((void**)&bufH, g_bufH);
    float* outp = (float*)d_out;

    const int NB = cdiv(NN, 1024);
    // CSR build
    k_init_cnt<<<cdiv(NN, 256), 256>>>();
    k_count<<<cdiv(NE, 256), 256>>>(dst);
    k_scan1<<<NB, 1024>>>();
    k_scan2<<<1, 128>>>(NB);
    k_scan3<<<NB, 1024>>>();
    k_self<<<cdiv(NN, 256), 256>>>();
    k_edges<<<cdiv(NE, 256), 256>>>(src, dst);

    const int TPB = 256;
    int blocks16 = cdiv(cdiv(NN, 2) * 32, TPB);   // SUB=16
    int blocks8  = cdiv(cdiv(NN, 4) * 32, TPB);   // SUB=8
    int blocks4  = cdiv(cdiv(NN, 8) * 32, TPB);   // SUB=4 scalar C=3
    int blocksN  = cdiv(NN, TPB);                 // thread-per-node

    // encoder
    k_eg1<<<blocks4, TPB>>>(x, W[0], B[0], bufB);                        // fused agg+eg1
    gemm_t<0, false, true>(bufB, W[1], nullptr, bufH, 160, 80);          // eg2 matmul -> fp16
    k_aggvh<80, 16, 1, true><<<blocks16, TPB>>>(bufH, B[1], bufA);       // eg2 agg+b+relu
    gemm_t<0, false, true>(bufA, W[2], nullptr, bufH, 80, 40);           // eg3 matmul -> fp16
    k_aggvh<40, 8, 1, true><<<blocks8, TPB>>>(bufH, B[2], bufB);         // eg3 agg+b+relu
    k_dense<40, 20, 0, false, false><<<blocksN, TPB>>>(bufB, W[3], nullptr, bufA);  // eg4 matmul
    k_aggv<20, 8, 1, true><<<blocks8, TPB>>>(bufA, B[3], bufB);          // eg4 agg+b+relu
    // latent dense chain
    k_chain<<<blocksN, TPB>>>(bufB, bufA, W[4], B[4], W[5], B[5], W[6], B[6], W[7], B[7]);
    // decoder
    k_aggv<20, 8, 0, false><<<blocks8, TPB>>>(bufA, nullptr, bufB);      // dg1 agg
    k_dense<20, 40, 1, true, true><<<blocksN, TPB>>>(bufB, W[8], B[8], bufH);       // dg1 -> fp16
    k_aggvh<40, 8, 0, false><<<blocks8, TPB>>>(bufH, nullptr, bufA);     // dg2 agg
    gemm_t<1, true, true>(bufA, W[9], B[9], bufH, 40, 80);               // dg2 relu -> fp16
    k_aggvh<80, 16, 0, false><<<blocks16, TPB>>>(bufH, nullptr, bufB);   // dg3 agg
    gemm_t<1, true, false>(bufB, W[10], B[10], bufA, 80, 160);           // dg3 relu
    k_dense<160, 3, 0, false, false><<<blocksN, TPB>>>(bufA, W[11], nullptr, bufB); // dg4 matmul
    k_agg3<2, true><<<blocks4, TPB>>>(bufB, B[11], outp);                // dg4 agg+b+tanh
}